// round 12
// baseline (speedup 1.0000x reference)
#include <cuda_runtime.h>
#include <cuda_bf16.h>
#include <stdint.h>
#include <math.h>

#define B_ 4
#define T_ 4096
#define D_ 1024
#define H_ 8
#define DH_ 128
#define NTOK (B_ * T_)          // 16384
#define NEGV (-1000000.0f)
#define NSPLIT 16
#define EP 272                  // padded smem row stride (bytes) for 128 bf16

// ---------------- scratch (device globals; no allocations allowed) ----------
__device__ __nv_bfloat16 g_xnh[(size_t)NTOK * D_];     // 32 MB xn (bf16)
__device__ __nv_bfloat16 g_wth[(size_t)3 * D_ * D_];   // 6 MB  W^T (q,k,v) bf16
__device__ __nv_bfloat16 g_qb[(size_t)NTOK * D_];      // 32 MB q softmaxed bf16
__device__ __nv_bfloat16 g_kb[(size_t)NTOK * D_];      // 32 MB k (masked) bf16
__device__ __nv_bfloat16 g_vb[(size_t)NTOK * D_];      // 32 MB v (masked) bf16
__device__ float g_attp[(size_t)NSPLIT * B_ * H_ * DH_ * DH_];  // 32 MB
__device__ float g_Sp[(size_t)NSPLIT * B_ * D_];
__device__ __nv_bfloat16 g_attb[(size_t)B_ * H_ * DH_ * DH_];   // 1 MB

// ======================= PTX helpers (sm_103 baseline ISA only) ==============
__device__ __forceinline__ uint32_t smem_u32(const void* p) {
    uint32_t a;
    asm("{ .reg .u64 t; cvta.to.shared.u64 t, %1; cvt.u32.u64 %0, t; }"
        : "=r"(a) : "l"(p));
    return a;
}
__device__ __forceinline__ void cp16(uint32_t d, const void* g) {
    asm volatile("cp.async.cg.shared.global [%0], [%1], 16;" :: "r"(d), "l"(g));
}
#define CP_COMMIT()  asm volatile("cp.async.commit_group;")
#define CP_WAIT(n)   asm volatile("cp.async.wait_group %0;" :: "n"(n) : "memory")
#define SW128(o) ((uint32_t)(o) ^ ((((uint32_t)(o)) >> 3) & 0x70))

__device__ __forceinline__ void ldsm_x4(uint32_t* r, uint32_t a) {
    asm volatile("ldmatrix.sync.aligned.m8n8.x4.shared.b16 {%0,%1,%2,%3}, [%4];"
                 : "=r"(r[0]), "=r"(r[1]), "=r"(r[2]), "=r"(r[3]) : "r"(a));
}
__device__ __forceinline__ void ldsm_x4t(uint32_t* r, uint32_t a) {
    asm volatile("ldmatrix.sync.aligned.m8n8.x4.trans.shared.b16 {%0,%1,%2,%3}, [%4];"
                 : "=r"(r[0]), "=r"(r[1]), "=r"(r[2]), "=r"(r[3]) : "r"(a));
}
__device__ __forceinline__ void mma16816(float* d, const uint32_t* a,
                                         const uint32_t* b) {
    asm volatile("mma.sync.aligned.m16n8k16.row.col.f32.bf16.bf16.f32 "
                 "{%0,%1,%2,%3}, {%4,%5,%6,%7}, {%8,%9}, {%0,%1,%2,%3};"
                 : "+f"(d[0]), "+f"(d[1]), "+f"(d[2]), "+f"(d[3])
                 : "r"(a[0]), "r"(a[1]), "r"(a[2]), "r"(a[3]),
                   "r"(b[0]), "r"(b[1]));
}
__device__ __forceinline__ uint32_t pack_bf16(float a, float b) {
    __nv_bfloat162 p = __floats2bfloat162_rn(a, b);
    return *(uint32_t*)&p;
}

// ---------------- LayerNorm: one block per token; emits bf16 ----------------
__global__ void __launch_bounds__(256) ln_kernel(const float* __restrict__ x,
                                                 const float* __restrict__ gamma,
                                                 const float* __restrict__ beta) {
    __shared__ float red[16];
    const int row = blockIdx.x;
    const int tid = threadIdx.x;
    const float4 v = ((const float4*)(x + (size_t)row * D_))[tid];
    float s  = v.x + v.y + v.z + v.w;
    float ss = v.x * v.x + v.y * v.y + v.z * v.z + v.w * v.w;
#pragma unroll
    for (int o = 16; o > 0; o >>= 1) {
        s  += __shfl_xor_sync(0xffffffffu, s, o);
        ss += __shfl_xor_sync(0xffffffffu, ss, o);
    }
    const int warp = tid >> 5, lane = tid & 31;
    if (lane == 0) { red[warp] = s; red[warp + 8] = ss; }
    __syncthreads();
    if (tid < 32) {
        float a = (tid < 8) ? red[tid] : 0.f;
        float b = (tid < 8) ? red[tid + 8] : 0.f;
#pragma unroll
        for (int o = 4; o > 0; o >>= 1) {
            a += __shfl_xor_sync(0xffffffffu, a, o);
            b += __shfl_xor_sync(0xffffffffu, b, o);
        }
        if (tid == 0) { red[0] = a; red[1] = b; }
    }
    __syncthreads();
    const float mu   = red[0] * (1.0f / D_);
    const float var  = red[1] * (1.0f / D_) - mu * mu;
    const float rstd = rsqrtf(var + 1e-5f);
    const float4 g  = ((const float4*)gamma)[tid];
    const float4 bb = ((const float4*)beta)[tid];
    const float o0 = (v.x - mu) * rstd * g.x + bb.x;
    const float o1 = (v.y - mu) * rstd * g.y + bb.y;
    const float o2 = (v.z - mu) * rstd * g.z + bb.z;
    const float o3 = (v.w - mu) * rstd * g.w + bb.w;
    const size_t off = (size_t)row * D_ + tid * 4;
    *(__nv_bfloat162*)(g_xnh + off)     = __floats2bfloat162_rn(o0, o1);
    *(__nv_bfloat162*)(g_xnh + off + 2) = __floats2bfloat162_rn(o2, o3);
}

// ---------------- W transpose to bf16: Wt[n][k] = W[k][n] --------------------
__global__ void __launch_bounds__(256) wsplit_kernel(const float* __restrict__ Wq,
                                                     const float* __restrict__ Wk,
                                                     const float* __restrict__ Wv) {
    __shared__ float t[32][33];
    const float* W = (blockIdx.z == 0) ? Wq : (blockIdx.z == 1) ? Wk : Wv;
    __nv_bfloat16* oh = g_wth + ((size_t)blockIdx.z << 20);
    const int tid = threadIdx.x;
    const int tx = tid & 31, ty = tid >> 5;
    const int bn = blockIdx.x * 32, bk = blockIdx.y * 32;
#pragma unroll
    for (int r = ty; r < 32; r += 8)
        t[r][tx] = W[(size_t)(bk + r) * 1024 + bn + tx];
    __syncthreads();
#pragma unroll
    for (int r = ty; r < 32; r += 8)
        oh[(size_t)(bn + r) * 1024 + bk + tx] = __float2bfloat16_rn(t[tx][r]);
}

// ---------------- QKV GEMM via mma.sync bf16 + fused epilogues ---------------
// Tile 128(M) x 128(N), BK=64, 3-stage cp.async, 128 threads, 2 CTAs/SM.
// 4 warps: warp (wm 0..1, wn 0..1) owns 64x64 (min ldsm crossbar traffic).
#define OFF_A  0
#define OFF_B  16384
#define STG    32768
#define QK_SMEM (3 * STG + 1024)

__global__ void __launch_bounds__(128, 2)
qkv_mma(const float* __restrict__ bq, const float* __restrict__ bk_,
        const float* __restrict__ bv, const float* __restrict__ mask) {
    extern __shared__ char dsm[];
    const uint32_t base = (smem_u32(dsm) + 1023) & ~1023u;
    const int tid = threadIdx.x, lane = tid & 31, wid = tid >> 5;
    const int wm = wid & 1, wn = wid >> 1;
    const int mode = blockIdx.z;
    const int n0 = blockIdx.x * 128;
    const size_t m0 = (size_t)blockIdx.y * 128;

    const __nv_bfloat16* A = g_xnh;
    const __nv_bfloat16* Bw = g_wth + ((size_t)mode << 20);

    float acc[4][8][4];
#pragma unroll
    for (int i = 0; i < 4; i++)
#pragma unroll
        for (int j = 0; j < 8; j++)
#pragma unroll
            for (int q = 0; q < 4; q++) acc[i][j][q] = 0.f;

    auto issue = [&](int i) {
        const int k0 = i * 64;
        const uint32_t sb = base + (i % 3) * STG;
#pragma unroll
        for (int p = 0; p < 8; p++) {
            const int idx = p * 128 + tid;             // 0..1023
            const int r = idx >> 3, kc = idx & 7;
            const uint32_t sw = SW128(r * 128 + kc * 16);
            cp16(sb + OFF_A + sw, A + (m0 + r) * 1024 + k0 + kc * 8);
            cp16(sb + OFF_B + sw, Bw + (size_t)(n0 + r) * 1024 + k0 + kc * 8);
        }
        CP_COMMIT();
    };

    issue(0); issue(1);
    const int arow  = wm * 64 + (lane & 15);
    const int acolb = (lane >> 4) * 16;
    const int brow  = wn * 64 + (lane & 7) + ((lane & 16) ? 8 : 0);
    const int bcolb = (lane & 8) ? 16 : 0;

    for (int i = 0; i < 16; i++) {
        if (i + 2 < 16) CP_WAIT(1); else CP_WAIT(0);
        __syncthreads();               // stage (i-1) consumers drained
        if (i + 2 < 16) issue(i + 2);  // overwrites stage (i-1)%3: safe
        const uint32_t sb = base + (i % 3) * STG;

#pragma unroll
        for (int ks = 0; ks < 4; ks++) {
            const int kb = ks * 32;
            uint32_t ah[4][4];
#pragma unroll
            for (int mi = 0; mi < 4; mi++) {
                const uint32_t ao = SW128((arow + mi * 16) * 128 + kb + acolb);
                ldsm_x4(ah[mi], sb + OFF_A + ao);
            }
#pragma unroll
            for (int nb = 0; nb < 4; nb++) {
                const uint32_t bo = SW128((brow + nb * 16) * 128 + kb + bcolb);
                uint32_t bh[4];
                ldsm_x4(bh, sb + OFF_B + bo);
#pragma unroll
                for (int mi = 0; mi < 4; mi++)
#pragma unroll
                    for (int ns = 0; ns < 2; ns++)
                        mma16816(acc[mi][nb * 2 + ns], ah[mi], &bh[ns * 2]);
            }
        }
    }
    __syncthreads();                   // mainloop fully drained before reuse

    const int rl0 = wm * 64 + (lane >> 2);            // local row base
    const int cl0 = wn * 64 + (lane & 3) * 2;         // local col base

    if (mode == 0) {
        // ---- fused q softmax: tile = one head (128 cols) per CTA ----
        float* S = (float*)dsm;                        // 128 x 128 fp32 (64KB)
#pragma unroll
        for (int mi = 0; mi < 4; mi++) {
            const int r0 = rl0 + mi * 16;
#pragma unroll
            for (int ni = 0; ni < 8; ni++) {
                const int c = cl0 + ni * 8;
                *(float2*)&S[(r0)     * 128 + c] = make_float2(acc[mi][ni][0], acc[mi][ni][1]);
                *(float2*)&S[(r0 + 8) * 128 + c] = make_float2(acc[mi][ni][2], acc[mi][ni][3]);
            }
        }
        __syncthreads();
        const float4 bias4 = *(const float4*)(bq + n0 + lane * 4);
#pragma unroll
        for (int u = wid * 32; u < wid * 32 + 32; u++) {
            float4 v = *(const float4*)&S[u * 128 + lane * 4];
            v.x += bias4.x; v.y += bias4.y; v.z += bias4.z; v.w += bias4.w;
            float mx = fmaxf(fmaxf(v.x, v.y), fmaxf(v.z, v.w));
#pragma unroll
            for (int o = 16; o > 0; o >>= 1)
                mx = fmaxf(mx, __shfl_xor_sync(0xffffffffu, mx, o));
            v.x = __expf(v.x - mx); v.y = __expf(v.y - mx);
            v.z = __expf(v.z - mx); v.w = __expf(v.w - mx);
            float sm = v.x + v.y + v.z + v.w;
#pragma unroll
            for (int o = 16; o > 0; o >>= 1)
                sm += __shfl_xor_sync(0xffffffffu, sm, o);
            const float inv = 1.0f / sm;
            uint2 pk;
            pk.x = pack_bf16(v.x * inv, v.y * inv);
            pk.y = pack_bf16(v.z * inv, v.w * inv);
            *(uint2*)(g_qb + (m0 + u) * 1024 + n0 + lane * 4) = pk;
        }
    } else {
        const float* bias = (mode == 1) ? bk_ : bv;
        __nv_bfloat16* __restrict__ C = (mode == 1) ? g_kb : g_vb;
#pragma unroll
        for (int mi = 0; mi < 4; mi++) {
            const int r0 = (int)m0 + rl0 + mi * 16;
            const int r1 = r0 + 8;
            const float mk0 = mask[r0], mk1 = mask[r1];
            const float ma0 = (mode == 1) ? (1.0f - mk0) * NEGV : 0.f;
            const float ma1 = (mode == 1) ? (1.0f - mk1) * NEGV : 0.f;
            const float mm0 = (mode == 2) ? mk0 : 1.f;
            const float mm1 = (mode == 2) ? mk1 : 1.f;
#pragma unroll
            for (int ni = 0; ni < 8; ni++) {
                const int c = n0 + cl0 + ni * 8;
                const float b0 = bias[c], b1 = bias[c + 1];
                *(uint32_t*)(C + (size_t)r0 * 1024 + c) =
                    pack_bf16((acc[mi][ni][0] + b0 + ma0) * mm0,
                              (acc[mi][ni][1] + b1 + ma0) * mm0);
                *(uint32_t*)(C + (size_t)r1 * 1024 + c) =
                    pack_bf16((acc[mi][ni][2] + b0 + ma1) * mm1,
                              (acc[mi][ni][3] + b1 + ma1) * mm1);
            }
        }
    }
}

// ---------------- att partial via HMMA, double-buffered cp.async K+V --------
// E = exp(k) computed in SMEM (masked rows: k=-1e6 -> exp==0 exactly).
__global__ void __launch_bounds__(256) att_part_kernel() {
    __shared__ __align__(16) char Kb[2][32 * EP];
    __shared__ __align__(16) char Vb[2][32 * EP];
    __shared__ float Sred[8][128];
    const int bh = blockIdx.x, sp = blockIdx.y;
    const int b = bh >> 3, h = bh & 7;
    const int tid = threadIdx.x, lane = tid & 31, wid = tid >> 5;
    const int wd = wid & 3, wl = wid >> 2;

    float acc[2][8][4];
#pragma unroll
    for (int i = 0; i < 2; i++)
#pragma unroll
        for (int j = 0; j < 8; j++)
#pragma unroll
            for (int q = 0; q < 4; q++) acc[i][j][q] = 0.f;
    float ssum[4] = {0.f, 0.f, 0.f, 0.f};

    const uint32_t Kbase[2] = { smem_u32(Kb[0]), smem_u32(Kb[1]) };
    const uint32_t Vbase[2] = { smem_u32(Vb[0]), smem_u32(Vb[1]) };
    const size_t gbase = ((size_t)b * T_) * D_ + h * 128;
    const int tstart = sp * (T_ / NSPLIT);
    const int dc = (tid & 31) * 4;

    auto issueKV = [&](int t0, int buf) {
#pragma unroll
        for (int it = 0; it < 2; it++) {
            const int idx = it * 256 + tid;            // 0..511
            const int tr = idx >> 4, ch = idx & 15;
            const size_t go = gbase + (size_t)(t0 + tr) * D_ + ch * 8;
            cp16(Kbase[buf] + tr * EP + ch * 16, g_kb + go);
            cp16(Vbase[buf] + tr * EP + ch * 16, g_vb + go);
        }
        CP_COMMIT();
    };

    issueKV(tstart, 0);
    for (int i = 0; i < 8; i++) {
        const int buf = i & 1;
        CP_WAIT(0);
        __syncthreads();               // data ready + prev iter fully done
        if (i + 1 < 8) issueKV(tstart + (i + 1) * 32, (i + 1) & 1);

        // E = exp(k) in place, from SMEM; masked rows give exactly 0
        int myvalid = 0;
#pragma unroll
        for (int s = 0; s < 4; s++) {
            const int tr = wid + s * 8;
            const uint32_t addr = tr * EP + dc * 2;
            const uint2 kp = *(const uint2*)(Kb[buf] + addr);
            const __nv_bfloat162 k01 = *(const __nv_bfloat162*)&kp.x;
            const __nv_bfloat162 k23 = *(const __nv_bfloat162*)&kp.y;
            const float e0 = __expf(__bfloat162float(k01.x));
            const float e1 = __expf(__bfloat162float(k01.y));
            const float e2 = __expf(__bfloat162float(k23.x));
            const float e3 = __expf(__bfloat162float(k23.y));
            ssum[0] += e0; ssum[1] += e1; ssum[2] += e2; ssum[3] += e3;
            if (e0 + e1 + e2 + e3 != 0.f) myvalid = 1;
            uint2 pe;
            pe.x = pack_bf16(e0, e1);
            pe.y = pack_bf16(e2, e3);
            *(uint2*)(Kb[buf] + addr) = pe;
        }
        const int anyvalid = __syncthreads_or(myvalid);
        if (anyvalid) {
#pragma unroll
            for (int ks = 0; ks < 2; ks++) {
                uint32_t a[2][4], bf[4][4];
#pragma unroll
                for (int mi = 0; mi < 2; mi++) {
                    const uint32_t ao = (uint32_t)((ks * 16 + ((lane & 16) ? 8 : 0)
                                       + (lane & 7)) * EP
                                       + (wd * 32 + mi * 16) * 2
                                       + ((lane & 8) ? 16 : 0));
                    ldsm_x4t(a[mi], Kbase[buf] + ao);
                }
#pragma unroll
                for (int nb = 0; nb < 4; nb++) {
                    const uint32_t bo = (uint32_t)((ks * 16 + ((lane & 8) ? 8 : 0)
                                       + (lane & 7)) * EP
                                       + (wl * 64 + nb * 16) * 2
                                       + ((lane & 16) ? 16 : 0));
                    ldsm_x4t(bf[nb], Vbase[buf] + bo);
                }
#pragma unroll
                for (int mi = 0; mi < 2; mi++)
#pragma unroll
                    for (int nb = 0; nb < 4; nb++)
#pragma unroll
                        for (int ns = 0; ns < 2; ns++)
                            mma16816(acc[mi][nb * 2 + ns], a[mi], &bf[nb][ns * 2]);
            }
        }
    }

    const size_t obase = ((size_t)sp * 32 + bh) * 16384;
#pragma unroll
    for (int mi = 0; mi < 2; mi++) {
        const int d0 = wd * 32 + mi * 16 + (lane >> 2);
#pragma unroll
        for (int ni = 0; ni < 8; ni++) {
            const int l0 = wl * 64 + ni * 8 + (lane & 3) * 2;
            *(float2*)(g_attp + obase + (size_t)d0 * 128 + l0) =
                make_float2(acc[mi][ni][0], acc[mi][ni][1]);
            *(float2*)(g_attp + obase + (size_t)(d0 + 8) * 128 + l0) =
                make_float2(acc[mi][ni][2], acc[mi][ni][3]);
        }
    }
#pragma unroll
    for (int j = 0; j < 4; j++) Sred[wid][dc + j] = ssum[j];
    __syncthreads();
    if (tid < 128) {
        float s = 0.f;
#pragma unroll
        for (int r = 0; r < 8; r++) s += Sred[r][tid];
        g_Sp[(size_t)sp * 4096 + bh * 128 + tid] = s;
    }
}

// ---------------- att reduce: sum partials, normalize, emit bf16 -------------
__global__ void __launch_bounds__(256) att_reduce_kernel() {
    __shared__ float Ss[16];
    const int bh = blockIdx.x, ch = blockIdx.y;
    const int tid = threadIdx.x;
    if (tid < 16) {
        const int d = ch * 16 + tid;
        float s = 0.f;
#pragma unroll
        for (int p = 0; p < NSPLIT; p++) s += g_Sp[(size_t)p * 4096 + bh * 128 + d];
        Ss[tid] = 1.0f / s;
    }
    __syncthreads();
    const int e0 = ch * 2048;
#pragma unroll
    for (int q = 0; q < 8; q++) {
        const int e = e0 + q * 256 + tid;
        float s = 0.f;
#pragma unroll
        for (int p = 0; p < NSPLIT; p++) s += g_attp[((size_t)p * 32 + bh) * 16384 + e];
        g_attb[(size_t)bh * 16384 + e] =
            __float2bfloat16_rn(s * Ss[(e >> 7) - ch * 16]);
    }
}

// ---------------- y = q_sm @ att via HMMA, out = x + y -----------------------
#define YG_SMEM (2 * 128 * EP + 256)
__global__ void __launch_bounds__(256) ygemm_kernel(const float* __restrict__ x,
                                                    float* __restrict__ out) {
    extern __shared__ char ydsm[];
    const uint32_t qs = (smem_u32(ydsm) + 15) & ~15u;
    const uint32_t as = qs + 128 * EP;
    const int bh = blockIdx.y, mt = blockIdx.x;
    const int b = bh >> 3, h = bh & 7;
    const int tid = threadIdx.x, lane = tid & 31, wid = tid >> 5;
    const int wm = wid & 3, wl = wid >> 2;

    const size_t qgbase = ((size_t)b * T_ + mt * 128) * D_ + h * 128;
    const size_t agbase = (size_t)bh * 16384;
#pragma unroll
    for (int p = 0; p < 8; p++) {
        const int idx = p * 256 + tid;
        const int r = idx >> 4, c8 = idx & 15;
        cp16(qs + r * EP + c8 * 16, g_qb + qgbase + (size_t)r * 1024 + c8 * 8);
        cp16(as + r * EP + c8 * 16, g_attb + agbase + (size_t)r * 128 + c8 * 8);
    }
    CP_COMMIT();
    CP_WAIT(0);
    __syncthreads();

    float acc[2][8][4];
#pragma unroll
    for (int i = 0; i < 2; i++)
#pragma unroll
        for (int j = 0; j < 8; j++)
#pragma unroll
            for (int q = 0; q < 4; q++) acc[i][j][q] = 0.f;

#pragma unroll
    for (int ks = 0; ks < 8; ks++) {
        uint32_t a[2][4], bf[4][4];
#pragma unroll
        for (int mi = 0; mi < 2; mi++) {
            const uint32_t ao = (uint32_t)((wm * 32 + mi * 16 + (lane & 15)) * EP
                               + ks * 32 + ((lane & 16) ? 16 : 0));
            ldsm_x4(a[mi], qs + ao);
        }
#pragma unroll
        for (int nb = 0; nb < 4; nb++) {
            const uint32_t bo = (uint32_t)((ks * 16 + ((lane & 8) ? 8 : 0)
                               + (lane & 7)) * EP
                               + (wl * 64 + nb * 16) * 2
                               + ((lane & 16) ? 16 : 0));
            ldsm_x4t(bf[nb], as + bo);
        }
#pragma unroll
        for (int mi = 0; mi < 2; mi++)
#pragma unroll
            for (int nb = 0; nb < 4; nb++)
#pragma unroll
                for (int ns = 0; ns < 2; ns++)
                    mma16816(acc[mi][nb * 2 + ns], a[mi], &bf[nb][ns * 2]);
    }

#pragma unroll
    for (int mi = 0; mi < 2; mi++) {
        const size_t row0 = (size_t)b * T_ + mt * 128 + wm * 32 + mi * 16 + (lane >> 2);
        const size_t row1 = row0 + 8;
#pragma unroll
        for (int ni = 0; ni < 8; ni++) {
            const int c = h * 128 + wl * 64 + ni * 8 + (lane & 3) * 2;
            const float2 x0 = *(const float2*)(x + row0 * 1024 + c);
            const float2 x1 = *(const float2*)(x + row1 * 1024 + c);
            float2 o0, o1;
            o0.x = acc[mi][ni][0] + x0.x; o0.y = acc[mi][ni][1] + x0.y;
            o1.x = acc[mi][ni][2] + x1.x; o1.y = acc[mi][ni][3] + x1.y;
            *(float2*)(out + row0 * 1024 + c) = o0;
            *(float2*)(out + row1 * 1024 + c) = o1;
        }
    }
}

// ---------------- launcher ---------------------------------------------------
extern "C" void kernel_launch(void* const* d_in, const int* in_sizes, int n_in,
                              void* d_out, int out_size) {
    const float* x     = (const float*)d_in[0];
    const float* mask  = (const float*)d_in[1];
    const float* Wq    = (const float*)d_in[2];
    const float* bq    = (const float*)d_in[3];
    const float* Wk    = (const float*)d_in[4];
    const float* bk    = (const float*)d_in[5];
    const float* Wv    = (const float*)d_in[6];
    const float* bv    = (const float*)d_in[7];
    const float* gamma = (const float*)d_in[8];
    const float* beta  = (const float*)d_in[9];
    float* out = (float*)d_out;

    static int smem_set = 0;
    if (!smem_set) {
        cudaFuncSetAttribute(qkv_mma, cudaFuncAttributeMaxDynamicSharedMemorySize,
                             QK_SMEM);
        cudaFuncSetAttribute(ygemm_kernel,
                             cudaFuncAttributeMaxDynamicSharedMemorySize, YG_SMEM);
        smem_set = 1;
    }

    ln_kernel<<<NTOK, 256>>>(x, gamma, beta);
    wsplit_kernel<<<dim3(32, 32, 3), 256>>>(Wq, Wk, Wv);

    qkv_mma<<<dim3(8, 128, 3), 128, QK_SMEM>>>(bq, bk, bv, mask);

    att_part_kernel<<<dim3(32, NSPLIT), 256>>>();
    att_reduce_kernel<<<dim3(32, 8), 256>>>();

    ygemm_kernel<<<dim3(32, 32), 256, YG_SMEM>>>(x, out);
}

// round 13
// speedup vs baseline: 1.0062x; 1.0062x over previous
#include <cuda_runtime.h>
#include <cuda_bf16.h>
#include <stdint.h>
#include <math.h>

#define B_ 4
#define T_ 4096
#define D_ 1024
#define H_ 8
#define DH_ 128
#define NTOK (B_ * T_)          // 16384
#define NEGV (-1000000.0f)
#define NSPLIT 16
#define EP 272                  // padded smem row stride (bytes) for 128 bf16

// ---------------- scratch (device globals; no allocations allowed) ----------
__device__ __nv_bfloat16 g_xnh[(size_t)NTOK * D_];     // 32 MB xn (bf16)
__device__ __nv_bfloat16 g_wth[(size_t)3 * D_ * D_];   // 6 MB  W^T (q,k,v) bf16
__device__ __nv_bfloat16 g_qb[(size_t)NTOK * D_];      // 32 MB q softmaxed bf16
__device__ __nv_bfloat16 g_kb[(size_t)NTOK * D_];      // 32 MB k (masked) bf16
__device__ __nv_bfloat16 g_vb[(size_t)NTOK * D_];      // 32 MB v (masked) bf16
__device__ float g_attp[(size_t)NSPLIT * B_ * H_ * DH_ * DH_];  // 32 MB
__device__ float g_Sp[(size_t)NSPLIT * B_ * D_];
__device__ __nv_bfloat16 g_attb[(size_t)B_ * H_ * DH_ * DH_];   // 1 MB

// ======================= PTX helpers (sm_103 baseline ISA only) ==============
__device__ __forceinline__ uint32_t smem_u32(const void* p) {
    uint32_t a;
    asm("{ .reg .u64 t; cvta.to.shared.u64 t, %1; cvt.u32.u64 %0, t; }"
        : "=r"(a) : "l"(p));
    return a;
}
__device__ __forceinline__ void cp16(uint32_t d, const void* g) {
    asm volatile("cp.async.cg.shared.global [%0], [%1], 16;" :: "r"(d), "l"(g));
}
#define CP_COMMIT()  asm volatile("cp.async.commit_group;")
#define CP_WAIT(n)   asm volatile("cp.async.wait_group %0;" :: "n"(n) : "memory")
#define SW128(o) ((uint32_t)(o) ^ ((((uint32_t)(o)) >> 3) & 0x70))

__device__ __forceinline__ void ldsm_x4(uint32_t* r, uint32_t a) {
    asm volatile("ldmatrix.sync.aligned.m8n8.x4.shared.b16 {%0,%1,%2,%3}, [%4];"
                 : "=r"(r[0]), "=r"(r[1]), "=r"(r[2]), "=r"(r[3]) : "r"(a));
}
__device__ __forceinline__ void ldsm_x4t(uint32_t* r, uint32_t a) {
    asm volatile("ldmatrix.sync.aligned.m8n8.x4.trans.shared.b16 {%0,%1,%2,%3}, [%4];"
                 : "=r"(r[0]), "=r"(r[1]), "=r"(r[2]), "=r"(r[3]) : "r"(a));
}
__device__ __forceinline__ void mma16816(float* d, const uint32_t* a,
                                         const uint32_t* b) {
    asm volatile("mma.sync.aligned.m16n8k16.row.col.f32.bf16.bf16.f32 "
                 "{%0,%1,%2,%3}, {%4,%5,%6,%7}, {%8,%9}, {%0,%1,%2,%3};"
                 : "+f"(d[0]), "+f"(d[1]), "+f"(d[2]), "+f"(d[3])
                 : "r"(a[0]), "r"(a[1]), "r"(a[2]), "r"(a[3]),
                   "r"(b[0]), "r"(b[1]));
}
__device__ __forceinline__ uint32_t pack_bf16(float a, float b) {
    __nv_bfloat162 p = __floats2bfloat162_rn(a, b);
    return *(uint32_t*)&p;
}

// ---------------- LayerNorm: one block per token; emits bf16 ----------------
__global__ void __launch_bounds__(256) ln_kernel(const float* __restrict__ x,
                                                 const float* __restrict__ gamma,
                                                 const float* __restrict__ beta) {
    __shared__ float red[16];
    const int row = blockIdx.x;
    const int tid = threadIdx.x;
    const float4 v = ((const float4*)(x + (size_t)row * D_))[tid];
    float s  = v.x + v.y + v.z + v.w;
    float ss = v.x * v.x + v.y * v.y + v.z * v.z + v.w * v.w;
#pragma unroll
    for (int o = 16; o > 0; o >>= 1) {
        s  += __shfl_xor_sync(0xffffffffu, s, o);
        ss += __shfl_xor_sync(0xffffffffu, ss, o);
    }
    const int warp = tid >> 5, lane = tid & 31;
    if (lane == 0) { red[warp] = s; red[warp + 8] = ss; }
    __syncthreads();
    if (tid < 32) {
        float a = (tid < 8) ? red[tid] : 0.f;
        float b = (tid < 8) ? red[tid + 8] : 0.f;
#pragma unroll
        for (int o = 4; o > 0; o >>= 1) {
            a += __shfl_xor_sync(0xffffffffu, a, o);
            b += __shfl_xor_sync(0xffffffffu, b, o);
        }
        if (tid == 0) { red[0] = a; red[1] = b; }
    }
    __syncthreads();
    const float mu   = red[0] * (1.0f / D_);
    const float var  = red[1] * (1.0f / D_) - mu * mu;
    const float rstd = rsqrtf(var + 1e-5f);
    const float4 g  = ((const float4*)gamma)[tid];
    const float4 bb = ((const float4*)beta)[tid];
    const float o0 = (v.x - mu) * rstd * g.x + bb.x;
    const float o1 = (v.y - mu) * rstd * g.y + bb.y;
    const float o2 = (v.z - mu) * rstd * g.z + bb.z;
    const float o3 = (v.w - mu) * rstd * g.w + bb.w;
    const size_t off = (size_t)row * D_ + tid * 4;
    *(__nv_bfloat162*)(g_xnh + off)     = __floats2bfloat162_rn(o0, o1);
    *(__nv_bfloat162*)(g_xnh + off + 2) = __floats2bfloat162_rn(o2, o3);
}

// ---------------- W transpose to bf16: Wt[n][k] = W[k][n] --------------------
__global__ void __launch_bounds__(256) wsplit_kernel(const float* __restrict__ Wq,
                                                     const float* __restrict__ Wk,
                                                     const float* __restrict__ Wv) {
    __shared__ float t[32][33];
    const float* W = (blockIdx.z == 0) ? Wq : (blockIdx.z == 1) ? Wk : Wv;
    __nv_bfloat16* oh = g_wth + ((size_t)blockIdx.z << 20);
    const int tid = threadIdx.x;
    const int tx = tid & 31, ty = tid >> 5;
    const int bn = blockIdx.x * 32, bk = blockIdx.y * 32;
#pragma unroll
    for (int r = ty; r < 32; r += 8)
        t[r][tx] = W[(size_t)(bk + r) * 1024 + bn + tx];
    __syncthreads();
#pragma unroll
    for (int r = ty; r < 32; r += 8)
        oh[(size_t)(bn + r) * 1024 + bk + tx] = __float2bfloat16_rn(t[tx][r]);
}

// ---------------- QKV GEMM via mma.sync bf16 + fused epilogues ---------------
// Tile 128(M) x 128(N), BK=64, 3-stage cp.async, 256 threads, 2 CTAs/SM.
// 8 warps: warp (wm 0..1, wn 0..3) owns 64x32.
// mode = mode_base + blockIdx.z (0:q+softmax, 1:k, 2:v).
#define OFF_A  0
#define OFF_B  16384
#define STG    32768
#define QK_SMEM (3 * STG + 1024)

__global__ void __launch_bounds__(256, 2)
qkv_mma(const float* __restrict__ bq, const float* __restrict__ bk_,
        const float* __restrict__ bv, const float* __restrict__ mask,
        int mode_base) {
    extern __shared__ char dsm[];
    const uint32_t base = (smem_u32(dsm) + 1023) & ~1023u;
    const int tid = threadIdx.x, lane = tid & 31, wid = tid >> 5;
    const int wm = wid & 1, wn = wid >> 1;
    const int mode = mode_base + blockIdx.z;
    const int n0 = blockIdx.x * 128;
    const size_t m0 = (size_t)blockIdx.y * 128;

    const __nv_bfloat16* A = g_xnh;
    const __nv_bfloat16* Bw = g_wth + ((size_t)mode << 20);

    float acc[4][4][4];
#pragma unroll
    for (int i = 0; i < 4; i++)
#pragma unroll
        for (int j = 0; j < 4; j++)
#pragma unroll
            for (int q = 0; q < 4; q++) acc[i][j][q] = 0.f;

    auto issue = [&](int i) {
        const int k0 = i * 64;
        const uint32_t sb = base + (i % 3) * STG;
#pragma unroll
        for (int p = 0; p < 4; p++) {
            const int idx = p * 256 + tid;             // 0..1023
            const int r = idx >> 3, kc = idx & 7;
            const uint32_t sw = SW128(r * 128 + kc * 16);
            cp16(sb + OFF_A + sw, A + (m0 + r) * 1024 + k0 + kc * 8);
            cp16(sb + OFF_B + sw, Bw + (size_t)(n0 + r) * 1024 + k0 + kc * 8);
        }
        CP_COMMIT();
    };

    issue(0); issue(1);
    const int arow  = wm * 64 + (lane & 15);
    const int acolb = (lane >> 4) * 16;
    const int brow  = wn * 32 + (lane & 7) + ((lane & 16) ? 8 : 0);
    const int bcolb = (lane & 8) ? 16 : 0;

    for (int i = 0; i < 16; i++) {
        if (i + 2 < 16) CP_WAIT(1); else CP_WAIT(0);
        __syncthreads();               // stage (i-1) consumers drained
        if (i + 2 < 16) issue(i + 2);  // overwrites stage (i-1)%3: safe
        const uint32_t sb = base + (i % 3) * STG;

#pragma unroll
        for (int ks = 0; ks < 4; ks++) {
            const int kb = ks * 32;
            uint32_t ah[4][4];
#pragma unroll
            for (int mi = 0; mi < 4; mi++) {
                const uint32_t ao = SW128((arow + mi * 16) * 128 + kb + acolb);
                ldsm_x4(ah[mi], sb + OFF_A + ao);
            }
#pragma unroll
            for (int nb = 0; nb < 2; nb++) {
                const uint32_t bo = SW128((brow + nb * 16) * 128 + kb + bcolb);
                uint32_t bh[4];
                ldsm_x4(bh, sb + OFF_B + bo);
#pragma unroll
                for (int mi = 0; mi < 4; mi++)
#pragma unroll
                    for (int ns = 0; ns < 2; ns++)
                        mma16816(acc[mi][nb * 2 + ns], ah[mi], &bh[ns * 2]);
            }
        }
    }
    __syncthreads();                   // mainloop fully drained before reuse

    const int rl0 = wm * 64 + (lane >> 2);            // local row base
    const int cl0 = wn * 32 + (lane & 3) * 2;         // local col base

    if (mode == 0) {
        // ---- fused q softmax: tile = one head (128 cols) per CTA ----
        float* S = (float*)dsm;                        // 128 x 128 fp32 (64KB)
#pragma unroll
        for (int mi = 0; mi < 4; mi++) {
            const int r0 = rl0 + mi * 16;
#pragma unroll
            for (int ni = 0; ni < 4; ni++) {
                const int c = cl0 + ni * 8;
                *(float2*)&S[(r0)     * 128 + c] = make_float2(acc[mi][ni][0], acc[mi][ni][1]);
                *(float2*)&S[(r0 + 8) * 128 + c] = make_float2(acc[mi][ni][2], acc[mi][ni][3]);
            }
        }
        __syncthreads();
        const float4 bias4 = *(const float4*)(bq + n0 + lane * 4);
#pragma unroll
        for (int u = wid * 16; u < wid * 16 + 16; u++) {
            float4 v = *(const float4*)&S[u * 128 + lane * 4];
            v.x += bias4.x; v.y += bias4.y; v.z += bias4.z; v.w += bias4.w;
            float mx = fmaxf(fmaxf(v.x, v.y), fmaxf(v.z, v.w));
#pragma unroll
            for (int o = 16; o > 0; o >>= 1)
                mx = fmaxf(mx, __shfl_xor_sync(0xffffffffu, mx, o));
            v.x = __expf(v.x - mx); v.y = __expf(v.y - mx);
            v.z = __expf(v.z - mx); v.w = __expf(v.w - mx);
            float sm = v.x + v.y + v.z + v.w;
#pragma unroll
            for (int o = 16; o > 0; o >>= 1)
                sm += __shfl_xor_sync(0xffffffffu, sm, o);
            const float inv = 1.0f / sm;
            uint2 pk;
            pk.x = pack_bf16(v.x * inv, v.y * inv);
            pk.y = pack_bf16(v.z * inv, v.w * inv);
            *(uint2*)(g_qb + (m0 + u) * 1024 + n0 + lane * 4) = pk;
        }
    } else {
        const float* bias = (mode == 1) ? bk_ : bv;
        __nv_bfloat16* __restrict__ C = (mode == 1) ? g_kb : g_vb;
#pragma unroll
        for (int mi = 0; mi < 4; mi++) {
            const int r0 = (int)m0 + rl0 + mi * 16;
            const int r1 = r0 + 8;
            const float mk0 = mask[r0], mk1 = mask[r1];
            const float ma0 = (mode == 1) ? (1.0f - mk0) * NEGV : 0.f;
            const float ma1 = (mode == 1) ? (1.0f - mk1) * NEGV : 0.f;
            const float mm0 = (mode == 2) ? mk0 : 1.f;
            const float mm1 = (mode == 2) ? mk1 : 1.f;
#pragma unroll
            for (int ni = 0; ni < 4; ni++) {
                const int c = n0 + cl0 + ni * 8;
                const float b0 = bias[c], b1 = bias[c + 1];
                *(uint32_t*)(C + (size_t)r0 * 1024 + c) =
                    pack_bf16((acc[mi][ni][0] + b0 + ma0) * mm0,
                              (acc[mi][ni][1] + b1 + ma0) * mm0);
                *(uint32_t*)(C + (size_t)r1 * 1024 + c) =
                    pack_bf16((acc[mi][ni][2] + b0 + ma1) * mm1,
                              (acc[mi][ni][3] + b1 + ma1) * mm1);
            }
        }
    }
}

// ---------------- att partial via HMMA, double-buffered cp.async K+V --------
// E = exp(k) computed in SMEM (masked rows: k=-1e6 -> exp==0 exactly).
__global__ void __launch_bounds__(256) att_part_kernel() {
    __shared__ __align__(16) char Kb[2][32 * EP];
    __shared__ __align__(16) char Vb[2][32 * EP];
    __shared__ float Sred[8][128];
    const int bh = blockIdx.x, sp = blockIdx.y;
    const int b = bh >> 3, h = bh & 7;
    const int tid = threadIdx.x, lane = tid & 31, wid = tid >> 5;
    const int wd = wid & 3, wl = wid >> 2;

    float acc[2][8][4];
#pragma unroll
    for (int i = 0; i < 2; i++)
#pragma unroll
        for (int j = 0; j < 8; j++)
#pragma unroll
            for (int q = 0; q < 4; q++) acc[i][j][q] = 0.f;
    float ssum[4] = {0.f, 0.f, 0.f, 0.f};

    const uint32_t Kbase[2] = { smem_u32(Kb[0]), smem_u32(Kb[1]) };
    const uint32_t Vbase[2] = { smem_u32(Vb[0]), smem_u32(Vb[1]) };
    const size_t gbase = ((size_t)b * T_) * D_ + h * 128;
    const int tstart = sp * (T_ / NSPLIT);
    const int dc = (tid & 31) * 4;

    auto issueKV = [&](int t0, int buf) {
#pragma unroll
        for (int it = 0; it < 2; it++) {
            const int idx = it * 256 + tid;            // 0..511
            const int tr = idx >> 4, ch = idx & 15;
            const size_t go = gbase + (size_t)(t0 + tr) * D_ + ch * 8;
            cp16(Kbase[buf] + tr * EP + ch * 16, g_kb + go);
            cp16(Vbase[buf] + tr * EP + ch * 16, g_vb + go);
        }
        CP_COMMIT();
    };

    issueKV(tstart, 0);
    for (int i = 0; i < 8; i++) {
        const int buf = i & 1;
        CP_WAIT(0);
        __syncthreads();               // data ready + prev iter fully done
        if (i + 1 < 8) issueKV(tstart + (i + 1) * 32, (i + 1) & 1);

        // E = exp(k) in place, from SMEM; masked rows give exactly 0
        int myvalid = 0;
#pragma unroll
        for (int s = 0; s < 4; s++) {
            const int tr = wid + s * 8;
            const uint32_t addr = tr * EP + dc * 2;
            const uint2 kp = *(const uint2*)(Kb[buf] + addr);
            const __nv_bfloat162 k01 = *(const __nv_bfloat162*)&kp.x;
            const __nv_bfloat162 k23 = *(const __nv_bfloat162*)&kp.y;
            const float e0 = __expf(__bfloat162float(k01.x));
            const float e1 = __expf(__bfloat162float(k01.y));
            const float e2 = __expf(__bfloat162float(k23.x));
            const float e3 = __expf(__bfloat162float(k23.y));
            ssum[0] += e0; ssum[1] += e1; ssum[2] += e2; ssum[3] += e3;
            if (e0 + e1 + e2 + e3 != 0.f) myvalid = 1;
            uint2 pe;
            pe.x = pack_bf16(e0, e1);
            pe.y = pack_bf16(e2, e3);
            *(uint2*)(Kb[buf] + addr) = pe;
        }
        const int anyvalid = __syncthreads_or(myvalid);
        if (anyvalid) {
#pragma unroll
            for (int ks = 0; ks < 2; ks++) {
                uint32_t a[2][4], bf[4][4];
#pragma unroll
                for (int mi = 0; mi < 2; mi++) {
                    const uint32_t ao = (uint32_t)((ks * 16 + ((lane & 16) ? 8 : 0)
                                       + (lane & 7)) * EP
                                       + (wd * 32 + mi * 16) * 2
                                       + ((lane & 8) ? 16 : 0));
                    ldsm_x4t(a[mi], Kbase[buf] + ao);
                }
#pragma unroll
                for (int nb = 0; nb < 4; nb++) {
                    const uint32_t bo = (uint32_t)((ks * 16 + ((lane & 8) ? 8 : 0)
                                       + (lane & 7)) * EP
                                       + (wl * 64 + nb * 16) * 2
                                       + ((lane & 16) ? 16 : 0));
                    ldsm_x4t(bf[nb], Vbase[buf] + bo);
                }
#pragma unroll
                for (int mi = 0; mi < 2; mi++)
#pragma unroll
                    for (int nb = 0; nb < 4; nb++)
#pragma unroll
                        for (int ns = 0; ns < 2; ns++)
                            mma16816(acc[mi][nb * 2 + ns], a[mi], &bf[nb][ns * 2]);
            }
        }
    }

    const size_t obase = ((size_t)sp * 32 + bh) * 16384;
#pragma unroll
    for (int mi = 0; mi < 2; mi++) {
        const int d0 = wd * 32 + mi * 16 + (lane >> 2);
#pragma unroll
        for (int ni = 0; ni < 8; ni++) {
            const int l0 = wl * 64 + ni * 8 + (lane & 3) * 2;
            *(float2*)(g_attp + obase + (size_t)d0 * 128 + l0) =
                make_float2(acc[mi][ni][0], acc[mi][ni][1]);
            *(float2*)(g_attp + obase + (size_t)(d0 + 8) * 128 + l0) =
                make_float2(acc[mi][ni][2], acc[mi][ni][3]);
        }
    }
#pragma unroll
    for (int j = 0; j < 4; j++) Sred[wid][dc + j] = ssum[j];
    __syncthreads();
    if (tid < 128) {
        float s = 0.f;
#pragma unroll
        for (int r = 0; r < 8; r++) s += Sred[r][tid];
        g_Sp[(size_t)sp * 4096 + bh * 128 + tid] = s;
    }
}

// ---------------- att reduce: sum partials, normalize, emit bf16 -------------
__global__ void __launch_bounds__(256) att_reduce_kernel() {
    __shared__ float Ss[16];
    const int bh = blockIdx.x, ch = blockIdx.y;
    const int tid = threadIdx.x;
    if (tid < 16) {
        const int d = ch * 16 + tid;
        float s = 0.f;
#pragma unroll
        for (int p = 0; p < NSPLIT; p++) s += g_Sp[(size_t)p * 4096 + bh * 128 + d];
        Ss[tid] = 1.0f / s;
    }
    __syncthreads();
    const int e0 = ch * 2048;
#pragma unroll
    for (int q = 0; q < 8; q++) {
        const int e = e0 + q * 256 + tid;
        float s = 0.f;
#pragma unroll
        for (int p = 0; p < NSPLIT; p++) s += g_attp[((size_t)p * 32 + bh) * 16384 + e];
        g_attb[(size_t)bh * 16384 + e] =
            __float2bfloat16_rn(s * Ss[(e >> 7) - ch * 16]);
    }
}

// ---------------- y = q_sm @ att via HMMA, out = x + y -----------------------
#define YG_SMEM (2 * 128 * EP + 256)
__global__ void __launch_bounds__(256) ygemm_kernel(const float* __restrict__ x,
                                                    float* __restrict__ out) {
    extern __shared__ char ydsm[];
    const uint32_t qs = (smem_u32(ydsm) + 15) & ~15u;
    const uint32_t as = qs + 128 * EP;
    const int bh = blockIdx.y, mt = blockIdx.x;
    const int b = bh >> 3, h = bh & 7;
    const int tid = threadIdx.x, lane = tid & 31, wid = tid >> 5;
    const int wm = wid & 3, wl = wid >> 2;

    const size_t qgbase = ((size_t)b * T_ + mt * 128) * D_ + h * 128;
    const size_t agbase = (size_t)bh * 16384;
#pragma unroll
    for (int p = 0; p < 8; p++) {
        const int idx = p * 256 + tid;
        const int r = idx >> 4, c8 = idx & 15;
        cp16(qs + r * EP + c8 * 16, g_qb + qgbase + (size_t)r * 1024 + c8 * 8);
        cp16(as + r * EP + c8 * 16, g_attb + agbase + (size_t)r * 128 + c8 * 8);
    }
    CP_COMMIT();
    CP_WAIT(0);
    __syncthreads();

    float acc[2][8][4];
#pragma unroll
    for (int i = 0; i < 2; i++)
#pragma unroll
        for (int j = 0; j < 8; j++)
#pragma unroll
            for (int q = 0; q < 4; q++) acc[i][j][q] = 0.f;

#pragma unroll
    for (int ks = 0; ks < 8; ks++) {
        uint32_t a[2][4], bf[4][4];
#pragma unroll
        for (int mi = 0; mi < 2; mi++) {
            const uint32_t ao = (uint32_t)((wm * 32 + mi * 16 + (lane & 15)) * EP
                               + ks * 32 + ((lane & 16) ? 16 : 0));
            ldsm_x4(a[mi], qs + ao);
        }
#pragma unroll
        for (int nb = 0; nb < 4; nb++) {
            const uint32_t bo = (uint32_t)((ks * 16 + ((lane & 8) ? 8 : 0)
                               + (lane & 7)) * EP
                               + (wl * 64 + nb * 16) * 2
                               + ((lane & 16) ? 16 : 0));
            ldsm_x4t(bf[nb], as + bo);
        }
#pragma unroll
        for (int mi = 0; mi < 2; mi++)
#pragma unroll
            for (int nb = 0; nb < 4; nb++)
#pragma unroll
                for (int ns = 0; ns < 2; ns++)
                    mma16816(acc[mi][nb * 2 + ns], a[mi], &bf[nb][ns * 2]);
    }

#pragma unroll
    for (int mi = 0; mi < 2; mi++) {
        const size_t row0 = (size_t)b * T_ + mt * 128 + wm * 32 + mi * 16 + (lane >> 2);
        const size_t row1 = row0 + 8;
#pragma unroll
        for (int ni = 0; ni < 8; ni++) {
            const int c = h * 128 + wl * 64 + ni * 8 + (lane & 3) * 2;
            const float2 x0 = *(const float2*)(x + row0 * 1024 + c);
            const float2 x1 = *(const float2*)(x + row1 * 1024 + c);
            float2 o0, o1;
            o0.x = acc[mi][ni][0] + x0.x; o0.y = acc[mi][ni][1] + x0.y;
            o1.x = acc[mi][ni][2] + x1.x; o1.y = acc[mi][ni][3] + x1.y;
            *(float2*)(out + row0 * 1024 + c) = o0;
            *(float2*)(out + row1 * 1024 + c) = o1;
        }
    }
}

// ---------------- launcher (fork-join: q path overlaps att path) -------------
extern "C" void kernel_launch(void* const* d_in, const int* in_sizes, int n_in,
                              void* d_out, int out_size) {
    const float* x     = (const float*)d_in[0];
    const float* mask  = (const float*)d_in[1];
    const float* Wq    = (const float*)d_in[2];
    const float* bq    = (const float*)d_in[3];
    const float* Wk    = (const float*)d_in[4];
    const float* bk    = (const float*)d_in[5];
    const float* Wv    = (const float*)d_in[6];
    const float* bv    = (const float*)d_in[7];
    const float* gamma = (const float*)d_in[8];
    const float* beta  = (const float*)d_in[9];
    float* out = (float*)d_out;

    static cudaStream_t s1;
    static cudaEvent_t evPre, evQ;
    static int init_done = 0;
    if (!init_done) {
        cudaFuncSetAttribute(qkv_mma, cudaFuncAttributeMaxDynamicSharedMemorySize,
                             QK_SMEM);
        cudaFuncSetAttribute(ygemm_kernel,
                             cudaFuncAttributeMaxDynamicSharedMemorySize, YG_SMEM);
        cudaStreamCreateWithFlags(&s1, cudaStreamNonBlocking);
        cudaEventCreateWithFlags(&evPre, cudaEventDisableTiming);
        cudaEventCreateWithFlags(&evQ, cudaEventDisableTiming);
        init_done = 1;
    }

    ln_kernel<<<NTOK, 256>>>(x, gamma, beta);
    wsplit_kernel<<<dim3(32, 32, 3), 256>>>(Wq, Wk, Wv);
    cudaEventRecord(evPre, 0);

    // fork: q (mode 0) on s1, runs concurrently with the k/v + att chain
    cudaStreamWaitEvent(s1, evPre, 0);
    qkv_mma<<<dim3(8, 128, 1), 256, QK_SMEM, s1>>>(bq, bk, bv, mask, 0);
    cudaEventRecord(evQ, s1);

    // k,v (modes 1,2) then attention accumulation on the default stream
    qkv_mma<<<dim3(8, 128, 2), 256, QK_SMEM>>>(bq, bk, bv, mask, 1);
    att_part_kernel<<<dim3(32, NSPLIT), 256>>>();
    att_reduce_kernel<<<dim3(32, 8), 256>>>();

    // join: ygemm needs q (s1) and attb (default)
    cudaStreamWaitEvent(0, evQ, 0);
    ygemm_kernel<<<dim3(32, 32), 256, YG_SMEM>>>(x, out);
}

// round 15
// speedup vs baseline: 1.0151x; 1.0089x over previous
#include <cuda_runtime.h>
#include <cuda_bf16.h>
#include <stdint.h>
#include <math.h>

#define B_ 4
#define T_ 4096
#define D_ 1024
#define H_ 8
#define DH_ 128
#define NTOK (B_ * T_)          // 16384
#define NEGV (-1000000.0f)
#define NSPLIT 8
#define EP 272                  // padded smem row stride (bytes) for 128 bf16

// ---------------- scratch (device globals; no allocations allowed) ----------
__device__ __nv_bfloat16 g_xnh[(size_t)NTOK * D_];     // 32 MB xn (bf16)
__device__ __nv_bfloat16 g_wth[(size_t)3 * D_ * D_];   // 6 MB  W^T (q,k,v) bf16
__device__ __nv_bfloat16 g_qb[(size_t)NTOK * D_];      // 32 MB q softmaxed bf16
__device__ __nv_bfloat16 g_kb[(size_t)NTOK * D_];      // 32 MB k (masked) bf16
__device__ __nv_bfloat16 g_vb[(size_t)NTOK * D_];      // 32 MB v (masked) bf16
__device__ float g_attp[(size_t)NSPLIT * B_ * H_ * DH_ * DH_];  // 16 MB
__device__ float g_Sp[(size_t)NSPLIT * B_ * D_];
__device__ __nv_bfloat16 g_attb[(size_t)B_ * H_ * DH_ * DH_];   // 1 MB

// ======================= PTX helpers (sm_103 baseline ISA only) ==============
__device__ __forceinline__ uint32_t smem_u32(const void* p) {
    uint32_t a;
    asm("{ .reg .u64 t; cvta.to.shared.u64 t, %1; cvt.u32.u64 %0, t; }"
        : "=r"(a) : "l"(p));
    return a;
}
__device__ __forceinline__ void cp16(uint32_t d, const void* g) {
    asm volatile("cp.async.cg.shared.global [%0], [%1], 16;" :: "r"(d), "l"(g));
}
#define CP_COMMIT()  asm volatile("cp.async.commit_group;")
#define CP_WAIT(n)   asm volatile("cp.async.wait_group %0;" :: "n"(n) : "memory")
#define SW128(o) ((uint32_t)(o) ^ ((((uint32_t)(o)) >> 3) & 0x70))

__device__ __forceinline__ void ldsm_x4(uint32_t* r, uint32_t a) {
    asm volatile("ldmatrix.sync.aligned.m8n8.x4.shared.b16 {%0,%1,%2,%3}, [%4];"
                 : "=r"(r[0]), "=r"(r[1]), "=r"(r[2]), "=r"(r[3]) : "r"(a));
}
__device__ __forceinline__ void ldsm_x4t(uint32_t* r, uint32_t a) {
    asm volatile("ldmatrix.sync.aligned.m8n8.x4.trans.shared.b16 {%0,%1,%2,%3}, [%4];"
                 : "=r"(r[0]), "=r"(r[1]), "=r"(r[2]), "=r"(r[3]) : "r"(a));
}
__device__ __forceinline__ void mma16816(float* d, const uint32_t* a,
                                         const uint32_t* b) {
    asm volatile("mma.sync.aligned.m16n8k16.row.col.f32.bf16.bf16.f32 "
                 "{%0,%1,%2,%3}, {%4,%5,%6,%7}, {%8,%9}, {%0,%1,%2,%3};"
                 : "+f"(d[0]), "+f"(d[1]), "+f"(d[2]), "+f"(d[3])
                 : "r"(a[0]), "r"(a[1]), "r"(a[2]), "r"(a[3]),
                   "r"(b[0]), "r"(b[1]));
}
__device__ __forceinline__ uint32_t pack_bf16(float a, float b) {
    __nv_bfloat162 p = __floats2bfloat162_rn(a, b);
    return *(uint32_t*)&p;
}

// ---------------- LayerNorm: one block per token; emits bf16 ----------------
__global__ void __launch_bounds__(256) ln_kernel(const float* __restrict__ x,
                                                 const float* __restrict__ gamma,
                                                 const float* __restrict__ beta) {
    __shared__ float red[16];
    const int row = blockIdx.x;
    const int tid = threadIdx.x;
    const float4 v = ((const float4*)(x + (size_t)row * D_))[tid];
    float s  = v.x + v.y + v.z + v.w;
    float ss = v.x * v.x + v.y * v.y + v.z * v.z + v.w * v.w;
#pragma unroll
    for (int o = 16; o > 0; o >>= 1) {
        s  += __shfl_xor_sync(0xffffffffu, s, o);
        ss += __shfl_xor_sync(0xffffffffu, ss, o);
    }
    const int warp = tid >> 5, lane = tid & 31;
    if (lane == 0) { red[warp] = s; red[warp + 8] = ss; }
    __syncthreads();
    if (tid < 32) {
        float a = (tid < 8) ? red[tid] : 0.f;
        float b = (tid < 8) ? red[tid + 8] : 0.f;
#pragma unroll
        for (int o = 4; o > 0; o >>= 1) {
            a += __shfl_xor_sync(0xffffffffu, a, o);
            b += __shfl_xor_sync(0xffffffffu, b, o);
        }
        if (tid == 0) { red[0] = a; red[1] = b; }
    }
    __syncthreads();
    const float mu   = red[0] * (1.0f / D_);
    const float var  = red[1] * (1.0f / D_) - mu * mu;
    const float rstd = rsqrtf(var + 1e-5f);
    const float4 g  = ((const float4*)gamma)[tid];
    const float4 bb = ((const float4*)beta)[tid];
    const float o0 = (v.x - mu) * rstd * g.x + bb.x;
    const float o1 = (v.y - mu) * rstd * g.y + bb.y;
    const float o2 = (v.z - mu) * rstd * g.z + bb.z;
    const float o3 = (v.w - mu) * rstd * g.w + bb.w;
    const size_t off = (size_t)row * D_ + tid * 4;
    *(__nv_bfloat162*)(g_xnh + off)     = __floats2bfloat162_rn(o0, o1);
    *(__nv_bfloat162*)(g_xnh + off + 2) = __floats2bfloat162_rn(o2, o3);
}

// ---------------- W transpose to bf16: Wt[n][k] = W[k][n] --------------------
__global__ void __launch_bounds__(256) wsplit_kernel(const float* __restrict__ Wq,
                                                     const float* __restrict__ Wk,
                                                     const float* __restrict__ Wv) {
    __shared__ float t[32][33];
    const float* W = (blockIdx.z == 0) ? Wq : (blockIdx.z == 1) ? Wk : Wv;
    __nv_bfloat16* oh = g_wth + ((size_t)blockIdx.z << 20);
    const int tid = threadIdx.x;
    const int tx = tid & 31, ty = tid >> 5;
    const int bn = blockIdx.x * 32, bk = blockIdx.y * 32;
#pragma unroll
    for (int r = ty; r < 32; r += 8)
        t[r][tx] = W[(size_t)(bk + r) * 1024 + bn + tx];
    __syncthreads();
#pragma unroll
    for (int r = ty; r < 32; r += 8)
        oh[(size_t)(bn + r) * 1024 + bk + tx] = __float2bfloat16_rn(t[tx][r]);
}

// ---------------- QKV GEMM via mma.sync bf16 + fused epilogues ---------------
// Tile 128(M) x 128(N), BK=64, 3-stage cp.async, 256 threads, 2 CTAs/SM.
// 8 warps: warp (wm 0..1, wn 0..3) owns 64x32.
// mode = mode_base + blockIdx.z (0:q+softmax, 1:k, 2:v).
#define OFF_A  0
#define OFF_B  16384
#define STG    32768
#define QK_SMEM (3 * STG + 1024)

__global__ void __launch_bounds__(256, 2)
qkv_mma(const float* __restrict__ bq, const float* __restrict__ bk_,
        const float* __restrict__ bv, const float* __restrict__ mask,
        int mode_base) {
    extern __shared__ char dsm[];
    const uint32_t base = (smem_u32(dsm) + 1023) & ~1023u;
    const int tid = threadIdx.x, lane = tid & 31, wid = tid >> 5;
    const int wm = wid & 1, wn = wid >> 1;
    const int mode = mode_base + blockIdx.z;
    const int n0 = blockIdx.x * 128;
    const size_t m0 = (size_t)blockIdx.y * 128;

    const __nv_bfloat16* A = g_xnh;
    const __nv_bfloat16* Bw = g_wth + ((size_t)mode << 20);

    float acc[4][4][4];
#pragma unroll
    for (int i = 0; i < 4; i++)
#pragma unroll
        for (int j = 0; j < 4; j++)
#pragma unroll
            for (int q = 0; q < 4; q++) acc[i][j][q] = 0.f;

    auto issue = [&](int i) {
        const int k0 = i * 64;
        const uint32_t sb = base + (i % 3) * STG;
#pragma unroll
        for (int p = 0; p < 4; p++) {
            const int idx = p * 256 + tid;             // 0..1023
            const int r = idx >> 3, kc = idx & 7;
            const uint32_t sw = SW128(r * 128 + kc * 16);
            cp16(sb + OFF_A + sw, A + (m0 + r) * 1024 + k0 + kc * 8);
            cp16(sb + OFF_B + sw, Bw + (size_t)(n0 + r) * 1024 + k0 + kc * 8);
        }
        CP_COMMIT();
    };

    issue(0); issue(1);
    const int arow  = wm * 64 + (lane & 15);
    const int acolb = (lane >> 4) * 16;
    const int brow  = wn * 32 + (lane & 7) + ((lane & 16) ? 8 : 0);
    const int bcolb = (lane & 8) ? 16 : 0;

    for (int i = 0; i < 16; i++) {
        if (i + 2 < 16) CP_WAIT(1); else CP_WAIT(0);
        __syncthreads();               // stage (i-1) consumers drained
        if (i + 2 < 16) issue(i + 2);  // overwrites stage (i-1)%3: safe
        const uint32_t sb = base + (i % 3) * STG;

#pragma unroll
        for (int ks = 0; ks < 4; ks++) {
            const int kb = ks * 32;
            uint32_t ah[4][4];
#pragma unroll
            for (int mi = 0; mi < 4; mi++) {
                const uint32_t ao = SW128((arow + mi * 16) * 128 + kb + acolb);
                ldsm_x4(ah[mi], sb + OFF_A + ao);
            }
#pragma unroll
            for (int nb = 0; nb < 2; nb++) {
                const uint32_t bo = SW128((brow + nb * 16) * 128 + kb + bcolb);
                uint32_t bh[4];
                ldsm_x4(bh, sb + OFF_B + bo);
#pragma unroll
                for (int mi = 0; mi < 4; mi++)
#pragma unroll
                    for (int ns = 0; ns < 2; ns++)
                        mma16816(acc[mi][nb * 2 + ns], ah[mi], &bh[ns * 2]);
            }
        }
    }
    __syncthreads();                   // mainloop fully drained before reuse

    const int rl0 = wm * 64 + (lane >> 2);            // local row base
    const int cl0 = wn * 32 + (lane & 3) * 2;         // local col base

    if (mode == 0) {
        // ---- fused q softmax: tile = one head (128 cols) per CTA ----
        float* S = (float*)dsm;                        // 128 x 128 fp32 (64KB)
#pragma unroll
        for (int mi = 0; mi < 4; mi++) {
            const int r0 = rl0 + mi * 16;
#pragma unroll
            for (int ni = 0; ni < 4; ni++) {
                const int c = cl0 + ni * 8;
                *(float2*)&S[(r0)     * 128 + c] = make_float2(acc[mi][ni][0], acc[mi][ni][1]);
                *(float2*)&S[(r0 + 8) * 128 + c] = make_float2(acc[mi][ni][2], acc[mi][ni][3]);
            }
        }
        __syncthreads();
        const float4 bias4 = *(const float4*)(bq + n0 + lane * 4);
#pragma unroll
        for (int u = wid * 16; u < wid * 16 + 16; u++) {
            float4 v = *(const float4*)&S[u * 128 + lane * 4];
            v.x += bias4.x; v.y += bias4.y; v.z += bias4.z; v.w += bias4.w;
            float mx = fmaxf(fmaxf(v.x, v.y), fmaxf(v.z, v.w));
#pragma unroll
            for (int o = 16; o > 0; o >>= 1)
                mx = fmaxf(mx, __shfl_xor_sync(0xffffffffu, mx, o));
            v.x = __expf(v.x - mx); v.y = __expf(v.y - mx);
            v.z = __expf(v.z - mx); v.w = __expf(v.w - mx);
            float sm = v.x + v.y + v.z + v.w;
#pragma unroll
            for (int o = 16; o > 0; o >>= 1)
                sm += __shfl_xor_sync(0xffffffffu, sm, o);
            const float inv = 1.0f / sm;
            uint2 pk;
            pk.x = pack_bf16(v.x * inv, v.y * inv);
            pk.y = pack_bf16(v.z * inv, v.w * inv);
            *(uint2*)(g_qb + (m0 + u) * 1024 + n0 + lane * 4) = pk;
        }
    } else {
        const float* bias = (mode == 1) ? bk_ : bv;
        __nv_bfloat16* __restrict__ C = (mode == 1) ? g_kb : g_vb;
#pragma unroll
        for (int mi = 0; mi < 4; mi++) {
            const int r0 = (int)m0 + rl0 + mi * 16;
            const int r1 = r0 + 8;
            const float mk0 = mask[r0], mk1 = mask[r1];
            const float ma0 = (mode == 1) ? (1.0f - mk0) * NEGV : 0.f;
            const float ma1 = (mode == 1) ? (1.0f - mk1) * NEGV : 0.f;
            const float mm0 = (mode == 2) ? mk0 : 1.f;
            const float mm1 = (mode == 2) ? mk1 : 1.f;
#pragma unroll
            for (int ni = 0; ni < 4; ni++) {
                const int c = n0 + cl0 + ni * 8;
                const float b0 = bias[c], b1 = bias[c + 1];
                *(uint32_t*)(C + (size_t)r0 * 1024 + c) =
                    pack_bf16((acc[mi][ni][0] + b0 + ma0) * mm0,
                              (acc[mi][ni][1] + b1 + ma0) * mm0);
                *(uint32_t*)(C + (size_t)r1 * 1024 + c) =
                    pack_bf16((acc[mi][ni][2] + b0 + ma1) * mm1,
                              (acc[mi][ni][3] + b1 + ma1) * mm1);
            }
        }
    }
}

// ---------------- att partial via HMMA, double-buffered cp.async K+V --------
// Mask-gated tiles: fully-masked 32-t tiles skip loads AND compute.
#define NITER (T_ / NSPLIT / 32)       // 16
__global__ void __launch_bounds__(256) att_part_kernel(const float* __restrict__ mask) {
    __shared__ __align__(16) char Kb[2][32 * EP];
    __shared__ __align__(16) char Vb[2][32 * EP];
    __shared__ float Sred[8][128];
    __shared__ int valid[NITER];
    const int bh = blockIdx.x, sp = blockIdx.y;
    const int b = bh >> 3, h = bh & 7;
    const int tid = threadIdx.x, lane = tid & 31, wid = tid >> 5;
    const int wd = wid & 3, wl = wid >> 2;
    const int tstart = sp * (T_ / NSPLIT);

    // per-tile validity: thread tid covers t = tstart + 2*tid, +1
    if (tid < NITER) valid[tid] = 0;
    __syncthreads();
    {
        const int t = 2 * tid;
        if (mask[b * T_ + tstart + t] != 0.f || mask[b * T_ + tstart + t + 1] != 0.f)
            valid[t >> 5] = 1;         // benign race, all writers store 1
    }
    __syncthreads();

    float acc[2][8][4];
#pragma unroll
    for (int i = 0; i < 2; i++)
#pragma unroll
        for (int j = 0; j < 8; j++)
#pragma unroll
            for (int q = 0; q < 4; q++) acc[i][j][q] = 0.f;
    float ssum[4] = {0.f, 0.f, 0.f, 0.f};

    const uint32_t Kbase[2] = { smem_u32(Kb[0]), smem_u32(Kb[1]) };
    const uint32_t Vbase[2] = { smem_u32(Vb[0]), smem_u32(Vb[1]) };
    const size_t gbase = ((size_t)b * T_) * D_ + h * 128;
    const int dc = (tid & 31) * 4;

    auto issueKV = [&](int it, int buf) {
#pragma unroll
        for (int s = 0; s < 2; s++) {
            const int idx = s * 256 + tid;             // 0..511
            const int tr = idx >> 4, ch = idx & 15;
            const size_t go = gbase + (size_t)(tstart + it * 32 + tr) * D_ + ch * 8;
            cp16(Kbase[buf] + tr * EP + ch * 16, g_kb + go);
            cp16(Vbase[buf] + tr * EP + ch * 16, g_vb + go);
        }
        CP_COMMIT();
    };

    if (valid[0]) issueKV(0, 0);
    for (int i = 0; i < NITER; i++) {
        const int buf = i & 1;
        CP_WAIT(0);
        __syncthreads();               // data ready + prev iter fully done
        if (i + 1 < NITER && valid[i + 1]) issueKV(i + 1, (i + 1) & 1);
        if (!valid[i]) continue;

        // E = exp(k) in place, from SMEM; masked rows give exactly 0
#pragma unroll
        for (int s = 0; s < 4; s++) {
            const int tr = wid + s * 8;
            const uint32_t addr = tr * EP + dc * 2;
            const uint2 kp = *(const uint2*)(Kb[buf] + addr);
            const __nv_bfloat162 k01 = *(const __nv_bfloat162*)&kp.x;
            const __nv_bfloat162 k23 = *(const __nv_bfloat162*)&kp.y;
            const float e0 = __expf(__bfloat162float(k01.x));
            const float e1 = __expf(__bfloat162float(k01.y));
            const float e2 = __expf(__bfloat162float(k23.x));
            const float e3 = __expf(__bfloat162float(k23.y));
            ssum[0] += e0; ssum[1] += e1; ssum[2] += e2; ssum[3] += e3;
            uint2 pe;
            pe.x = pack_bf16(e0, e1);
            pe.y = pack_bf16(e2, e3);
            *(uint2*)(Kb[buf] + addr) = pe;
        }
        __syncthreads();
#pragma unroll
        for (int ks = 0; ks < 2; ks++) {
            uint32_t a[2][4], bf[4][4];
#pragma unroll
            for (int mi = 0; mi < 2; mi++) {
                const uint32_t ao = (uint32_t)((ks * 16 + ((lane & 16) ? 8 : 0)
                                   + (lane & 7)) * EP
                                   + (wd * 32 + mi * 16) * 2
                                   + ((lane & 8) ? 16 : 0));
                ldsm_x4t(a[mi], Kbase[buf] + ao);
            }
#pragma unroll
            for (int nb = 0; nb < 4; nb++) {
                const uint32_t bo = (uint32_t)((ks * 16 + ((lane & 8) ? 8 : 0)
                                   + (lane & 7)) * EP
                                   + (wl * 64 + nb * 16) * 2
                                   + ((lane & 16) ? 16 : 0));
                ldsm_x4t(bf[nb], Vbase[buf] + bo);
            }
#pragma unroll
            for (int mi = 0; mi < 2; mi++)
#pragma unroll
                for (int nb = 0; nb < 4; nb++)
#pragma unroll
                    for (int ns = 0; ns < 2; ns++)
                        mma16816(acc[mi][nb * 2 + ns], a[mi], &bf[nb][ns * 2]);
        }
    }

    const size_t obase = ((size_t)sp * 32 + bh) * 16384;
#pragma unroll
    for (int mi = 0; mi < 2; mi++) {
        const int d0 = wd * 32 + mi * 16 + (lane >> 2);
#pragma unroll
        for (int ni = 0; ni < 8; ni++) {
            const int l0 = wl * 64 + ni * 8 + (lane & 3) * 2;
            *(float2*)(g_attp + obase + (size_t)d0 * 128 + l0) =
                make_float2(acc[mi][ni][0], acc[mi][ni][1]);
            *(float2*)(g_attp + obase + (size_t)(d0 + 8) * 128 + l0) =
                make_float2(acc[mi][ni][2], acc[mi][ni][3]);
        }
    }
#pragma unroll
    for (int j = 0; j < 4; j++) Sred[wid][dc + j] = ssum[j];
    __syncthreads();
    if (tid < 128) {
        float s = 0.f;
#pragma unroll
        for (int r = 0; r < 8; r++) s += Sred[r][tid];
        g_Sp[(size_t)sp * 4096 + bh * 128 + tid] = s;
    }
}

// ---------------- att reduce: sum partials, normalize, emit bf16 -------------
__global__ void __launch_bounds__(256) att_reduce_kernel() {
    __shared__ float Ss[16];
    const int bh = blockIdx.x, ch = blockIdx.y;
    const int tid = threadIdx.x;
    if (tid < 16) {
        const int d = ch * 16 + tid;
        float s = 0.f;
#pragma unroll
        for (int p = 0; p < NSPLIT; p++) s += g_Sp[(size_t)p * 4096 + bh * 128 + d];
        Ss[tid] = 1.0f / s;
    }
    __syncthreads();
    const int e0 = ch * 2048;
#pragma unroll
    for (int q = 0; q < 8; q++) {
        const int e = e0 + q * 256 + tid;
        float s = 0.f;
#pragma unroll
        for (int p = 0; p < NSPLIT; p++) s += g_attp[((size_t)p * 32 + bh) * 16384 + e];
        g_attb[(size_t)bh * 16384 + e] =
            __float2bfloat16_rn(s * Ss[(e >> 7) - ch * 16]);
    }
}

// ---------------- y = q_sm @ att via HMMA, out = x + y -----------------------
#define YG_SMEM (2 * 128 * EP + 256)
__global__ void __launch_bounds__(256) ygemm_kernel(const float* __restrict__ x,
                                                    float* __restrict__ out) {
    extern __shared__ char ydsm[];
    const uint32_t qs = (smem_u32(ydsm) + 15) & ~15u;
    const uint32_t as = qs + 128 * EP;
    const int bh = blockIdx.y, mt = blockIdx.x;
    const int b = bh >> 3, h = bh & 7;
    const int tid = threadIdx.x, lane = tid & 31, wid = tid >> 5;
    const int wm = wid & 3, wl = wid >> 2;

    const size_t qgbase = ((size_t)b * T_ + mt * 128) * D_ + h * 128;
    const size_t agbase = (size_t)bh * 16384;
#pragma unroll
    for (int p = 0; p < 8; p++) {
        const int idx = p * 256 + tid;
        const int r = idx >> 4, c8 = idx & 15;
        cp16(qs + r * EP + c8 * 16, g_qb + qgbase + (size_t)r * 1024 + c8 * 8);
        cp16(as + r * EP + c8 * 16, g_attb + agbase + (size_t)r * 128 + c8 * 8);
    }
    CP_COMMIT();
    CP_WAIT(0);
    __syncthreads();

    float acc[2][8][4];
#pragma unroll
    for (int i = 0; i < 2; i++)
#pragma unroll
        for (int j = 0; j < 8; j++)
#pragma unroll
            for (int q = 0; q < 4; q++) acc[i][j][q] = 0.f;

#pragma unroll
    for (int ks = 0; ks < 8; ks++) {
        uint32_t a[2][4], bf[4][4];
#pragma unroll
        for (int mi = 0; mi < 2; mi++) {
            const uint32_t ao = (uint32_t)((wm * 32 + mi * 16 + (lane & 15)) * EP
                               + ks * 32 + ((lane & 16) ? 16 : 0));
            ldsm_x4(a[mi], qs + ao);
        }
#pragma unroll
        for (int nb = 0; nb < 4; nb++) {
            const uint32_t bo = (uint32_t)((ks * 16 + ((lane & 8) ? 8 : 0)
                               + (lane & 7)) * EP
                               + (wl * 64 + nb * 16) * 2
                               + ((lane & 16) ? 16 : 0));
            ldsm_x4t(bf[nb], as + bo);
        }
#pragma unroll
        for (int mi = 0; mi < 2; mi++)
#pragma unroll
            for (int nb = 0; nb < 4; nb++)
#pragma unroll
                for (int ns = 0; ns < 2; ns++)
                    mma16816(acc[mi][nb * 2 + ns], a[mi], &bf[nb][ns * 2]);
    }

#pragma unroll
    for (int mi = 0; mi < 2; mi++) {
        const size_t row0 = (size_t)b * T_ + mt * 128 + wm * 32 + mi * 16 + (lane >> 2);
        const size_t row1 = row0 + 8;
#pragma unroll
        for (int ni = 0; ni < 8; ni++) {
            const int c = h * 128 + wl * 64 + ni * 8 + (lane & 3) * 2;
            const float2 x0 = *(const float2*)(x + row0 * 1024 + c);
            const float2 x1 = *(const float2*)(x + row1 * 1024 + c);
            float2 o0, o1;
            o0.x = acc[mi][ni][0] + x0.x; o0.y = acc[mi][ni][1] + x0.y;
            o1.x = acc[mi][ni][2] + x1.x; o1.y = acc[mi][ni][3] + x1.y;
            *(float2*)(out + row0 * 1024 + c) = o0;
            *(float2*)(out + row1 * 1024 + c) = o1;
        }
    }
}

// ---------------- launcher (capture-legal priority fork-join) ----------------
extern "C" void kernel_launch(void* const* d_in, const int* in_sizes, int n_in,
                              void* d_out, int out_size) {
    const float* x     = (const float*)d_in[0];
    const float* mask  = (const float*)d_in[1];
    const float* Wq    = (const float*)d_in[2];
    const float* bq    = (const float*)d_in[3];
    const float* Wk    = (const float*)d_in[4];
    const float* bk    = (const float*)d_in[5];
    const float* Wv    = (const float*)d_in[6];
    const float* bv    = (const float*)d_in[7];
    const float* gamma = (const float*)d_in[8];
    const float* beta  = (const float*)d_in[9];
    float* out = (float*)d_out;

    static cudaStream_t s1;
    static cudaEvent_t evStart, evLn, evW, evQ;
    static int init_done = 0;
    if (!init_done) {
        cudaFuncSetAttribute(qkv_mma, cudaFuncAttributeMaxDynamicSharedMemorySize,
                             QK_SMEM);
        cudaFuncSetAttribute(ygemm_kernel,
                             cudaFuncAttributeMaxDynamicSharedMemorySize, YG_SMEM);
        int prLow, prHigh;
        cudaDeviceGetStreamPriorityRange(&prLow, &prHigh);
        cudaStreamCreateWithPriority(&s1, cudaStreamNonBlocking, prLow);
        cudaEventCreateWithFlags(&evStart, cudaEventDisableTiming);
        cudaEventCreateWithFlags(&evLn, cudaEventDisableTiming);
        cudaEventCreateWithFlags(&evW, cudaEventDisableTiming);
        cudaEventCreateWithFlags(&evQ, cudaEventDisableTiming);
        init_done = 1;
    }

    // Capture-legal fork: s1 work must begin with a wait on an event
    // recorded on the capture-origin stream (stream 0).
    cudaEventRecord(evStart, 0);
    cudaStreamWaitEvent(s1, evStart, 0);

    // s1 (low prio): wsplit (needs only W)
    wsplit_kernel<<<dim3(32, 32, 3), 256, 0, s1>>>(Wq, Wk, Wv);
    cudaEventRecord(evW, s1);

    // stream 0: ln (needs only x)
    ln_kernel<<<NTOK, 256>>>(x, gamma, beta);
    cudaEventRecord(evLn, 0);

    // stream 0: kv GEMM (modes 1,2) -> att chain
    cudaStreamWaitEvent(0, evW, 0);
    qkv_mma<<<dim3(8, 128, 2), 256, QK_SMEM>>>(bq, bk, bv, mask, 1);

    // s1 (low prio): q GEMM backfills around kv + att
    cudaStreamWaitEvent(s1, evLn, 0);
    qkv_mma<<<dim3(8, 128, 1), 256, QK_SMEM, s1>>>(bq, bk, bv, mask, 0);
    cudaEventRecord(evQ, s1);

    att_part_kernel<<<dim3(32, NSPLIT), 256>>>(mask);
    att_reduce_kernel<<<dim3(32, 8), 256>>>();

    // join: ygemm needs q (s1) and attb (stream 0)
    cudaStreamWaitEvent(0, evQ, 0);
    ygemm_kernel<<<dim3(32, 32), 256, YG_SMEM>>>(x, out);
}

// round 16
// speedup vs baseline: 1.0234x; 1.0082x over previous
#include <cuda_runtime.h>
#include <cuda_bf16.h>
#include <stdint.h>
#include <math.h>

#define B_ 4
#define T_ 4096
#define D_ 1024
#define H_ 8
#define DH_ 128
#define NTOK (B_ * T_)          // 16384
#define NEGV (-1000000.0f)
#define NSPLIT 8
#define EP 272                  // padded smem row stride (bytes) for 128 bf16

// ---------------- scratch (device globals; no allocations allowed) ----------
__device__ __nv_bfloat16 g_xnh[(size_t)NTOK * D_];     // 32 MB xn (bf16)
__device__ __nv_bfloat16 g_wth[(size_t)3 * D_ * D_];   // 6 MB  W^T (q,k,v) bf16
__device__ __nv_bfloat16 g_qb[(size_t)NTOK * D_];      // 32 MB q softmaxed bf16
__device__ __nv_bfloat16 g_kb[(size_t)NTOK * D_];      // 32 MB k (masked) bf16
__device__ __nv_bfloat16 g_vb[(size_t)NTOK * D_];      // 32 MB v (masked) bf16
__device__ float g_attp[(size_t)NSPLIT * B_ * H_ * DH_ * DH_];  // 16 MB
__device__ float g_Sp[(size_t)NSPLIT * B_ * D_];
__device__ __nv_bfloat16 g_attb[(size_t)B_ * H_ * DH_ * DH_];   // 1 MB

// ======================= PTX helpers (sm_103 baseline ISA only) ==============
__device__ __forceinline__ uint32_t smem_u32(const void* p) {
    uint32_t a;
    asm("{ .reg .u64 t; cvta.to.shared.u64 t, %1; cvt.u32.u64 %0, t; }"
        : "=r"(a) : "l"(p));
    return a;
}
__device__ __forceinline__ void cp16(uint32_t d, const void* g) {
    asm volatile("cp.async.cg.shared.global [%0], [%1], 16;" :: "r"(d), "l"(g));
}
#define CP_COMMIT()  asm volatile("cp.async.commit_group;")
#define CP_WAIT(n)   asm volatile("cp.async.wait_group %0;" :: "n"(n) : "memory")
#define SW128(o) ((uint32_t)(o) ^ ((((uint32_t)(o)) >> 3) & 0x70))

__device__ __forceinline__ void ldsm_x4(uint32_t* r, uint32_t a) {
    asm volatile("ldmatrix.sync.aligned.m8n8.x4.shared.b16 {%0,%1,%2,%3}, [%4];"
                 : "=r"(r[0]), "=r"(r[1]), "=r"(r[2]), "=r"(r[3]) : "r"(a));
}
__device__ __forceinline__ void ldsm_x4t(uint32_t* r, uint32_t a) {
    asm volatile("ldmatrix.sync.aligned.m8n8.x4.trans.shared.b16 {%0,%1,%2,%3}, [%4];"
                 : "=r"(r[0]), "=r"(r[1]), "=r"(r[2]), "=r"(r[3]) : "r"(a));
}
__device__ __forceinline__ void mma16816(float* d, const uint32_t* a,
                                         const uint32_t* b) {
    asm volatile("mma.sync.aligned.m16n8k16.row.col.f32.bf16.bf16.f32 "
                 "{%0,%1,%2,%3}, {%4,%5,%6,%7}, {%8,%9}, {%0,%1,%2,%3};"
                 : "+f"(d[0]), "+f"(d[1]), "+f"(d[2]), "+f"(d[3])
                 : "r"(a[0]), "r"(a[1]), "r"(a[2]), "r"(a[3]),
                   "r"(b[0]), "r"(b[1]));
}
__device__ __forceinline__ uint32_t pack_bf16(float a, float b) {
    __nv_bfloat162 p = __floats2bfloat162_rn(a, b);
    return *(uint32_t*)&p;
}

// ---------------- LayerNorm: one block per token; emits bf16 ----------------
__global__ void __launch_bounds__(256) ln_kernel(const float* __restrict__ x,
                                                 const float* __restrict__ gamma,
                                                 const float* __restrict__ beta) {
    __shared__ float red[16];
    const int row = blockIdx.x;
    const int tid = threadIdx.x;
    const float4 v = ((const float4*)(x + (size_t)row * D_))[tid];
    float s  = v.x + v.y + v.z + v.w;
    float ss = v.x * v.x + v.y * v.y + v.z * v.z + v.w * v.w;
#pragma unroll
    for (int o = 16; o > 0; o >>= 1) {
        s  += __shfl_xor_sync(0xffffffffu, s, o);
        ss += __shfl_xor_sync(0xffffffffu, ss, o);
    }
    const int warp = tid >> 5, lane = tid & 31;
    if (lane == 0) { red[warp] = s; red[warp + 8] = ss; }
    __syncthreads();
    if (tid < 32) {
        float a = (tid < 8) ? red[tid] : 0.f;
        float b = (tid < 8) ? red[tid + 8] : 0.f;
#pragma unroll
        for (int o = 4; o > 0; o >>= 1) {
            a += __shfl_xor_sync(0xffffffffu, a, o);
            b += __shfl_xor_sync(0xffffffffu, b, o);
        }
        if (tid == 0) { red[0] = a; red[1] = b; }
    }
    __syncthreads();
    const float mu   = red[0] * (1.0f / D_);
    const float var  = red[1] * (1.0f / D_) - mu * mu;
    const float rstd = rsqrtf(var + 1e-5f);
    const float4 g  = ((const float4*)gamma)[tid];
    const float4 bb = ((const float4*)beta)[tid];
    const float o0 = (v.x - mu) * rstd * g.x + bb.x;
    const float o1 = (v.y - mu) * rstd * g.y + bb.y;
    const float o2 = (v.z - mu) * rstd * g.z + bb.z;
    const float o3 = (v.w - mu) * rstd * g.w + bb.w;
    const size_t off = (size_t)row * D_ + tid * 4;
    *(__nv_bfloat162*)(g_xnh + off)     = __floats2bfloat162_rn(o0, o1);
    *(__nv_bfloat162*)(g_xnh + off + 2) = __floats2bfloat162_rn(o2, o3);
}

// ---------------- W transpose to bf16: Wt[n][k] = W[k][n] --------------------
__global__ void __launch_bounds__(256) wsplit_kernel(const float* __restrict__ Wq,
                                                     const float* __restrict__ Wk,
                                                     const float* __restrict__ Wv) {
    __shared__ float t[32][33];
    const float* W = (blockIdx.z == 0) ? Wq : (blockIdx.z == 1) ? Wk : Wv;
    __nv_bfloat16* oh = g_wth + ((size_t)blockIdx.z << 20);
    const int tid = threadIdx.x;
    const int tx = tid & 31, ty = tid >> 5;
    const int bn = blockIdx.x * 32, bk = blockIdx.y * 32;
#pragma unroll
    for (int r = ty; r < 32; r += 8)
        t[r][tx] = W[(size_t)(bk + r) * 1024 + bn + tx];
    __syncthreads();
#pragma unroll
    for (int r = ty; r < 32; r += 8)
        oh[(size_t)(bn + r) * 1024 + bk + tx] = __float2bfloat16_rn(t[tx][r]);
}

// ---------------- QKV GEMM via mma.sync bf16 + fused epilogues ---------------
// Tile 128(M) x 128(N), BK=64, 3-stage cp.async, 256 threads, 2 CTAs/SM.
// 8 warps: warp (wm 0..1, wn 0..3) owns 64x32.
// mode = mode_base + blockIdx.z (0:q+softmax, 1:k, 2:v).
#define OFF_A  0
#define OFF_B  16384
#define STG    32768
#define QK_SMEM (3 * STG + 1024)

__global__ void __launch_bounds__(256, 2)
qkv_mma(const float* __restrict__ bq, const float* __restrict__ bk_,
        const float* __restrict__ bv, const float* __restrict__ mask,
        int mode_base) {
    extern __shared__ char dsm[];
    const uint32_t base = (smem_u32(dsm) + 1023) & ~1023u;
    const int tid = threadIdx.x, lane = tid & 31, wid = tid >> 5;
    const int wm = wid & 1, wn = wid >> 1;
    const int mode = mode_base + blockIdx.z;
    const int n0 = blockIdx.x * 128;
    const size_t m0 = (size_t)blockIdx.y * 128;

    const __nv_bfloat16* A = g_xnh;
    const __nv_bfloat16* Bw = g_wth + ((size_t)mode << 20);

    float acc[4][4][4];
#pragma unroll
    for (int i = 0; i < 4; i++)
#pragma unroll
        for (int j = 0; j < 4; j++)
#pragma unroll
            for (int q = 0; q < 4; q++) acc[i][j][q] = 0.f;

    auto issue = [&](int i) {
        const int k0 = i * 64;
        const uint32_t sb = base + (i % 3) * STG;
#pragma unroll
        for (int p = 0; p < 4; p++) {
            const int idx = p * 256 + tid;             // 0..1023
            const int r = idx >> 3, kc = idx & 7;
            const uint32_t sw = SW128(r * 128 + kc * 16);
            cp16(sb + OFF_A + sw, A + (m0 + r) * 1024 + k0 + kc * 8);
            cp16(sb + OFF_B + sw, Bw + (size_t)(n0 + r) * 1024 + k0 + kc * 8);
        }
        CP_COMMIT();
    };

    issue(0); issue(1);
    const int arow  = wm * 64 + (lane & 15);
    const int acolb = (lane >> 4) * 16;
    const int brow  = wn * 32 + (lane & 7) + ((lane & 16) ? 8 : 0);
    const int bcolb = (lane & 8) ? 16 : 0;

    for (int i = 0; i < 16; i++) {
        if (i + 2 < 16) CP_WAIT(1); else CP_WAIT(0);
        __syncthreads();               // stage (i-1) consumers drained
        if (i + 2 < 16) issue(i + 2);  // overwrites stage (i-1)%3: safe
        const uint32_t sb = base + (i % 3) * STG;

#pragma unroll
        for (int ks = 0; ks < 4; ks++) {
            const int kb = ks * 32;
            uint32_t ah[4][4];
#pragma unroll
            for (int mi = 0; mi < 4; mi++) {
                const uint32_t ao = SW128((arow + mi * 16) * 128 + kb + acolb);
                ldsm_x4(ah[mi], sb + OFF_A + ao);
            }
#pragma unroll
            for (int nb = 0; nb < 2; nb++) {
                const uint32_t bo = SW128((brow + nb * 16) * 128 + kb + bcolb);
                uint32_t bh[4];
                ldsm_x4(bh, sb + OFF_B + bo);
#pragma unroll
                for (int mi = 0; mi < 4; mi++)
#pragma unroll
                    for (int ns = 0; ns < 2; ns++)
                        mma16816(acc[mi][nb * 2 + ns], ah[mi], &bh[ns * 2]);
            }
        }
    }
    __syncthreads();                   // mainloop fully drained before reuse

    const int rl0 = wm * 64 + (lane >> 2);            // local row base
    const int cl0 = wn * 32 + (lane & 3) * 2;         // local col base

    if (mode == 0) {
        // ---- fused q softmax: tile = one head (128 cols) per CTA ----
        float* S = (float*)dsm;                        // 128 x 128 fp32 (64KB)
#pragma unroll
        for (int mi = 0; mi < 4; mi++) {
            const int r0 = rl0 + mi * 16;
#pragma unroll
            for (int ni = 0; ni < 4; ni++) {
                const int c = cl0 + ni * 8;
                *(float2*)&S[(r0)     * 128 + c] = make_float2(acc[mi][ni][0], acc[mi][ni][1]);
                *(float2*)&S[(r0 + 8) * 128 + c] = make_float2(acc[mi][ni][2], acc[mi][ni][3]);
            }
        }
        __syncthreads();
        const float4 bias4 = *(const float4*)(bq + n0 + lane * 4);
#pragma unroll
        for (int u = wid * 16; u < wid * 16 + 16; u++) {
            float4 v = *(const float4*)&S[u * 128 + lane * 4];
            v.x += bias4.x; v.y += bias4.y; v.z += bias4.z; v.w += bias4.w;
            float mx = fmaxf(fmaxf(v.x, v.y), fmaxf(v.z, v.w));
#pragma unroll
            for (int o = 16; o > 0; o >>= 1)
                mx = fmaxf(mx, __shfl_xor_sync(0xffffffffu, mx, o));
            v.x = __expf(v.x - mx); v.y = __expf(v.y - mx);
            v.z = __expf(v.z - mx); v.w = __expf(v.w - mx);
            float sm = v.x + v.y + v.z + v.w;
#pragma unroll
            for (int o = 16; o > 0; o >>= 1)
                sm += __shfl_xor_sync(0xffffffffu, sm, o);
            const float inv = 1.0f / sm;
            uint2 pk;
            pk.x = pack_bf16(v.x * inv, v.y * inv);
            pk.y = pack_bf16(v.z * inv, v.w * inv);
            *(uint2*)(g_qb + (m0 + u) * 1024 + n0 + lane * 4) = pk;
        }
    } else {
        const float* bias = (mode == 1) ? bk_ : bv;
        __nv_bfloat16* __restrict__ C = (mode == 1) ? g_kb : g_vb;
#pragma unroll
        for (int mi = 0; mi < 4; mi++) {
            const int r0 = (int)m0 + rl0 + mi * 16;
            const int r1 = r0 + 8;
            const float mk0 = mask[r0], mk1 = mask[r1];
            const float ma0 = (mode == 1) ? (1.0f - mk0) * NEGV : 0.f;
            const float ma1 = (mode == 1) ? (1.0f - mk1) * NEGV : 0.f;
            const float mm0 = (mode == 2) ? mk0 : 1.f;
            const float mm1 = (mode == 2) ? mk1 : 1.f;
#pragma unroll
            for (int ni = 0; ni < 4; ni++) {
                const int c = n0 + cl0 + ni * 8;
                const float b0 = bias[c], b1 = bias[c + 1];
                *(uint32_t*)(C + (size_t)r0 * 1024 + c) =
                    pack_bf16((acc[mi][ni][0] + b0 + ma0) * mm0,
                              (acc[mi][ni][1] + b1 + ma0) * mm0);
                *(uint32_t*)(C + (size_t)r1 * 1024 + c) =
                    pack_bf16((acc[mi][ni][2] + b0 + ma1) * mm1,
                              (acc[mi][ni][3] + b1 + ma1) * mm1);
            }
        }
    }
}

// ---------------- att partial via HMMA, double-buffered cp.async K+V --------
// Mask-gated tiles: fully-masked 32-t tiles skip loads AND compute.
#define NITER (T_ / NSPLIT / 32)       // 16
__global__ void __launch_bounds__(256) att_part_kernel(const float* __restrict__ mask) {
    __shared__ __align__(16) char Kb[2][32 * EP];
    __shared__ __align__(16) char Vb[2][32 * EP];
    __shared__ float Sred[8][128];
    __shared__ int valid[NITER];
    const int bh = blockIdx.x, sp = blockIdx.y;
    const int b = bh >> 3, h = bh & 7;
    const int tid = threadIdx.x, lane = tid & 31, wid = tid >> 5;
    const int wd = wid & 3, wl = wid >> 2;
    const int tstart = sp * (T_ / NSPLIT);

    // per-tile validity: thread tid covers t = tstart + 2*tid, +1
    if (tid < NITER) valid[tid] = 0;
    __syncthreads();
    {
        const int t = 2 * tid;
        if (mask[b * T_ + tstart + t] != 0.f || mask[b * T_ + tstart + t + 1] != 0.f)
            valid[t >> 5] = 1;         // benign race, all writers store 1
    }
    __syncthreads();

    float acc[2][8][4];
#pragma unroll
    for (int i = 0; i < 2; i++)
#pragma unroll
        for (int j = 0; j < 8; j++)
#pragma unroll
            for (int q = 0; q < 4; q++) acc[i][j][q] = 0.f;
    float ssum[4] = {0.f, 0.f, 0.f, 0.f};

    const uint32_t Kbase[2] = { smem_u32(Kb[0]), smem_u32(Kb[1]) };
    const uint32_t Vbase[2] = { smem_u32(Vb[0]), smem_u32(Vb[1]) };
    const size_t gbase = ((size_t)b * T_) * D_ + h * 128;
    const int dc = (tid & 31) * 4;

    auto issueKV = [&](int it, int buf) {
#pragma unroll
        for (int s = 0; s < 2; s++) {
            const int idx = s * 256 + tid;             // 0..511
            const int tr = idx >> 4, ch = idx & 15;
            const size_t go = gbase + (size_t)(tstart + it * 32 + tr) * D_ + ch * 8;
            cp16(Kbase[buf] + tr * EP + ch * 16, g_kb + go);
            cp16(Vbase[buf] + tr * EP + ch * 16, g_vb + go);
        }
        CP_COMMIT();
    };

    if (valid[0]) issueKV(0, 0);
    for (int i = 0; i < NITER; i++) {
        const int buf = i & 1;
        CP_WAIT(0);
        __syncthreads();               // data ready + prev iter fully done
        if (i + 1 < NITER && valid[i + 1]) issueKV(i + 1, (i + 1) & 1);
        if (!valid[i]) continue;

        // E = exp(k) in place, from SMEM; masked rows give exactly 0
#pragma unroll
        for (int s = 0; s < 4; s++) {
            const int tr = wid + s * 8;
            const uint32_t addr = tr * EP + dc * 2;
            const uint2 kp = *(const uint2*)(Kb[buf] + addr);
            const __nv_bfloat162 k01 = *(const __nv_bfloat162*)&kp.x;
            const __nv_bfloat162 k23 = *(const __nv_bfloat162*)&kp.y;
            const float e0 = __expf(__bfloat162float(k01.x));
            const float e1 = __expf(__bfloat162float(k01.y));
            const float e2 = __expf(__bfloat162float(k23.x));
            const float e3 = __expf(__bfloat162float(k23.y));
            ssum[0] += e0; ssum[1] += e1; ssum[2] += e2; ssum[3] += e3;
            uint2 pe;
            pe.x = pack_bf16(e0, e1);
            pe.y = pack_bf16(e2, e3);
            *(uint2*)(Kb[buf] + addr) = pe;
        }
        __syncthreads();
#pragma unroll
        for (int ks = 0; ks < 2; ks++) {
            uint32_t a[2][4], bf[4][4];
#pragma unroll
            for (int mi = 0; mi < 2; mi++) {
                const uint32_t ao = (uint32_t)((ks * 16 + ((lane & 16) ? 8 : 0)
                                   + (lane & 7)) * EP
                                   + (wd * 32 + mi * 16) * 2
                                   + ((lane & 8) ? 16 : 0));
                ldsm_x4t(a[mi], Kbase[buf] + ao);
            }
#pragma unroll
            for (int nb = 0; nb < 4; nb++) {
                const uint32_t bo = (uint32_t)((ks * 16 + ((lane & 8) ? 8 : 0)
                                   + (lane & 7)) * EP
                                   + (wl * 64 + nb * 16) * 2
                                   + ((lane & 16) ? 16 : 0));
                ldsm_x4t(bf[nb], Vbase[buf] + bo);
            }
#pragma unroll
            for (int mi = 0; mi < 2; mi++)
#pragma unroll
                for (int nb = 0; nb < 4; nb++)
#pragma unroll
                    for (int ns = 0; ns < 2; ns++)
                        mma16816(acc[mi][nb * 2 + ns], a[mi], &bf[nb][ns * 2]);
        }
    }

    const size_t obase = ((size_t)sp * 32 + bh) * 16384;
#pragma unroll
    for (int mi = 0; mi < 2; mi++) {
        const int d0 = wd * 32 + mi * 16 + (lane >> 2);
#pragma unroll
        for (int ni = 0; ni < 8; ni++) {
            const int l0 = wl * 64 + ni * 8 + (lane & 3) * 2;
            *(float2*)(g_attp + obase + (size_t)d0 * 128 + l0) =
                make_float2(acc[mi][ni][0], acc[mi][ni][1]);
            *(float2*)(g_attp + obase + (size_t)(d0 + 8) * 128 + l0) =
                make_float2(acc[mi][ni][2], acc[mi][ni][3]);
        }
    }
#pragma unroll
    for (int j = 0; j < 4; j++) Sred[wid][dc + j] = ssum[j];
    __syncthreads();
    if (tid < 128) {
        float s = 0.f;
#pragma unroll
        for (int r = 0; r < 8; r++) s += Sred[r][tid];
        g_Sp[(size_t)sp * 4096 + bh * 128 + tid] = s;
    }
}

// ---------------- att reduce: sum partials, normalize, emit bf16 -------------
__global__ void __launch_bounds__(256) att_reduce_kernel() {
    __shared__ float Ss[16];
    const int bh = blockIdx.x, ch = blockIdx.y;
    const int tid = threadIdx.x;
    if (tid < 16) {
        const int d = ch * 16 + tid;
        float s = 0.f;
#pragma unroll
        for (int p = 0; p < NSPLIT; p++) s += g_Sp[(size_t)p * 4096 + bh * 128 + d];
        Ss[tid] = 1.0f / s;
    }
    __syncthreads();
    const int e0 = ch * 2048;
#pragma unroll
    for (int q = 0; q < 8; q++) {
        const int e = e0 + q * 256 + tid;
        float s = 0.f;
#pragma unroll
        for (int p = 0; p < NSPLIT; p++) s += g_attp[((size_t)p * 32 + bh) * 16384 + e];
        g_attb[(size_t)bh * 16384 + e] =
            __float2bfloat16_rn(s * Ss[(e >> 7) - ch * 16]);
    }
}

// ---------------- y = q_sm @ att via HMMA, out = x + y -----------------------
#define YG_SMEM (2 * 128 * EP + 256)
__global__ void __launch_bounds__(256) ygemm_kernel(const float* __restrict__ x,
                                                    float* __restrict__ out) {
    extern __shared__ char ydsm[];
    const uint32_t qs = (smem_u32(ydsm) + 15) & ~15u;
    const uint32_t as = qs + 128 * EP;
    const int bh = blockIdx.y, mt = blockIdx.x;
    const int b = bh >> 3, h = bh & 7;
    const int tid = threadIdx.x, lane = tid & 31, wid = tid >> 5;
    const int wm = wid & 3, wl = wid >> 2;

    const size_t qgbase = ((size_t)b * T_ + mt * 128) * D_ + h * 128;
    const size_t agbase = (size_t)bh * 16384;
#pragma unroll
    for (int p = 0; p < 8; p++) {
        const int idx = p * 256 + tid;
        const int r = idx >> 4, c8 = idx & 15;
        cp16(qs + r * EP + c8 * 16, g_qb + qgbase + (size_t)r * 1024 + c8 * 8);
        cp16(as + r * EP + c8 * 16, g_attb + agbase + (size_t)r * 128 + c8 * 8);
    }
    CP_COMMIT();
    CP_WAIT(0);
    __syncthreads();

    float acc[2][8][4];
#pragma unroll
    for (int i = 0; i < 2; i++)
#pragma unroll
        for (int j = 0; j < 8; j++)
#pragma unroll
            for (int q = 0; q < 4; q++) acc[i][j][q] = 0.f;

#pragma unroll
    for (int ks = 0; ks < 8; ks++) {
        uint32_t a[2][4], bf[4][4];
#pragma unroll
        for (int mi = 0; mi < 2; mi++) {
            const uint32_t ao = (uint32_t)((wm * 32 + mi * 16 + (lane & 15)) * EP
                               + ks * 32 + ((lane & 16) ? 16 : 0));
            ldsm_x4(a[mi], qs + ao);
        }
#pragma unroll
        for (int nb = 0; nb < 4; nb++) {
            const uint32_t bo = (uint32_t)((ks * 16 + ((lane & 8) ? 8 : 0)
                               + (lane & 7)) * EP
                               + (wl * 64 + nb * 16) * 2
                               + ((lane & 16) ? 16 : 0));
            ldsm_x4t(bf[nb], as + bo);
        }
#pragma unroll
        for (int mi = 0; mi < 2; mi++)
#pragma unroll
            for (int nb = 0; nb < 4; nb++)
#pragma unroll
                for (int ns = 0; ns < 2; ns++)
                    mma16816(acc[mi][nb * 2 + ns], a[mi], &bf[nb][ns * 2]);
    }

#pragma unroll
    for (int mi = 0; mi < 2; mi++) {
        const size_t row0 = (size_t)b * T_ + mt * 128 + wm * 32 + mi * 16 + (lane >> 2);
        const size_t row1 = row0 + 8;
#pragma unroll
        for (int ni = 0; ni < 8; ni++) {
            const int c = h * 128 + wl * 64 + ni * 8 + (lane & 3) * 2;
            const float2 x0 = *(const float2*)(x + row0 * 1024 + c);
            const float2 x1 = *(const float2*)(x + row1 * 1024 + c);
            float2 o0, o1;
            o0.x = acc[mi][ni][0] + x0.x; o0.y = acc[mi][ni][1] + x0.y;
            o1.x = acc[mi][ni][2] + x1.x; o1.y = acc[mi][ni][3] + x1.y;
            *(float2*)(out + row0 * 1024 + c) = o0;
            *(float2*)(out + row1 * 1024 + c) = o1;
        }
    }
}

// ---------------- launcher: q owns machine post-kv; att fills its slack ------
extern "C" void kernel_launch(void* const* d_in, const int* in_sizes, int n_in,
                              void* d_out, int out_size) {
    const float* x     = (const float*)d_in[0];
    const float* mask  = (const float*)d_in[1];
    const float* Wq    = (const float*)d_in[2];
    const float* bq    = (const float*)d_in[3];
    const float* Wk    = (const float*)d_in[4];
    const float* bk    = (const float*)d_in[5];
    const float* Wv    = (const float*)d_in[6];
    const float* bv    = (const float*)d_in[7];
    const float* gamma = (const float*)d_in[8];
    const float* beta  = (const float*)d_in[9];
    float* out = (float*)d_out;

    static cudaStream_t s1;
    static cudaEvent_t evStart, evKV, evATT;
    static int init_done = 0;
    if (!init_done) {
        cudaFuncSetAttribute(qkv_mma, cudaFuncAttributeMaxDynamicSharedMemorySize,
                             QK_SMEM);
        cudaFuncSetAttribute(ygemm_kernel,
                             cudaFuncAttributeMaxDynamicSharedMemorySize, YG_SMEM);
        int prLow, prHigh;
        cudaDeviceGetStreamPriorityRange(&prLow, &prHigh);
        cudaStreamCreateWithPriority(&s1, cudaStreamNonBlocking, prLow);
        cudaEventCreateWithFlags(&evStart, cudaEventDisableTiming);
        cudaEventCreateWithFlags(&evKV, cudaEventDisableTiming);
        cudaEventCreateWithFlags(&evATT, cudaEventDisableTiming);
        init_done = 1;
    }

    // Capture-legal fork: s1 begins by waiting on an event from stream 0.
    cudaEventRecord(evStart, 0);
    cudaStreamWaitEvent(s1, evStart, 0);

    // s1 (low prio): wsplit (needs only W)
    wsplit_kernel<<<dim3(32, 32, 3), 256, 0, s1>>>(Wq, Wk, Wv);

    // stream 0: ln (needs only x)
    ln_kernel<<<NTOK, 256>>>(x, gamma, beta);

    // stream 0 waits wsplit (join via event on s1 tail recorded below is for
    // att; for kv we need wsplit done -> use an event now)
    {
        static cudaEvent_t evW;
        static int w_init = 0;
        if (!w_init) { cudaEventCreateWithFlags(&evW, cudaEventDisableTiming); w_init = 1; }
        cudaEventRecord(evW, s1);
        cudaStreamWaitEvent(0, evW, 0);
    }

    // stream 0: kv GEMM (modes 1,2), then q GEMM immediately (owns machine)
    qkv_mma<<<dim3(8, 128, 2), 256, QK_SMEM>>>(bq, bk, bv, mask, 1);
    cudaEventRecord(evKV, 0);
    qkv_mma<<<dim3(8, 128, 1), 256, QK_SMEM>>>(bq, bk, bv, mask, 0);

    // s1 (low prio): att chain fills q's idle issue slots
    cudaStreamWaitEvent(s1, evKV, 0);
    att_part_kernel<<<dim3(32, NSPLIT), 256, 0, s1>>>(mask);
    att_reduce_kernel<<<dim3(32, 8), 256, 0, s1>>>();
    cudaEventRecord(evATT, s1);

    // join: ygemm needs q (stream 0 order) and attb (s1)
    cudaStreamWaitEvent(0, evATT, 0);
    ygemm_kernel<<<dim3(32, 32), 256, YG_SMEM>>>(x, out);
}

// round 17
// speedup vs baseline: 1.1236x; 1.0979x over previous
#include <cuda_runtime.h>
#include <cuda_bf16.h>
#include <stdint.h>
#include <math.h>

#define B_ 4
#define T_ 4096
#define D_ 1024
#define H_ 8
#define DH_ 128
#define NTOK (B_ * T_)          // 16384
#define NEGV (-1000000.0f)
#define NSPLIT 8
#define EP 272                  // padded smem row stride (bytes) for 128 bf16

// ---------------- scratch (device globals; no allocations allowed) ----------
__device__ __nv_bfloat16 g_xnh[(size_t)NTOK * D_];     // 32 MB xn (bf16)
__device__ __nv_bfloat16 g_wth[(size_t)3 * D_ * D_];   // 6 MB  W^T (q,k,v) bf16
__device__ __nv_bfloat16 g_qb[(size_t)NTOK * D_];      // 32 MB q softmaxed bf16
__device__ __nv_bfloat16 g_kb[(size_t)NTOK * D_];      // 32 MB k (masked) bf16
__device__ __nv_bfloat16 g_vb[(size_t)NTOK * D_];      // 32 MB v (masked) bf16
__device__ float g_attp[(size_t)NSPLIT * B_ * H_ * DH_ * DH_];  // 16 MB
__device__ float g_Sp[(size_t)NSPLIT * B_ * D_];
__device__ __nv_bfloat16 g_attb[(size_t)B_ * H_ * DH_ * DH_];   // 1 MB

// ======================= PTX helpers (sm_103 baseline ISA only) ==============
__device__ __forceinline__ uint32_t smem_u32(const void* p) {
    uint32_t a;
    asm("{ .reg .u64 t; cvta.to.shared.u64 t, %1; cvt.u32.u64 %0, t; }"
        : "=r"(a) : "l"(p));
    return a;
}
__device__ __forceinline__ void cp16(uint32_t d, const void* g) {
    asm volatile("cp.async.cg.shared.global [%0], [%1], 16;" :: "r"(d), "l"(g));
}
#define CP_COMMIT()  asm volatile("cp.async.commit_group;")
#define CP_WAIT(n)   asm volatile("cp.async.wait_group %0;" :: "n"(n) : "memory")
#define SW128(o) ((uint32_t)(o) ^ ((((uint32_t)(o)) >> 3) & 0x70))

__device__ __forceinline__ void ldsm_x4(uint32_t* r, uint32_t a) {
    asm volatile("ldmatrix.sync.aligned.m8n8.x4.shared.b16 {%0,%1,%2,%3}, [%4];"
                 : "=r"(r[0]), "=r"(r[1]), "=r"(r[2]), "=r"(r[3]) : "r"(a));
}
__device__ __forceinline__ void ldsm_x4t(uint32_t* r, uint32_t a) {
    asm volatile("ldmatrix.sync.aligned.m8n8.x4.trans.shared.b16 {%0,%1,%2,%3}, [%4];"
                 : "=r"(r[0]), "=r"(r[1]), "=r"(r[2]), "=r"(r[3]) : "r"(a));
}
__device__ __forceinline__ void mma16816(float* d, const uint32_t* a,
                                         const uint32_t* b) {
    asm volatile("mma.sync.aligned.m16n8k16.row.col.f32.bf16.bf16.f32 "
                 "{%0,%1,%2,%3}, {%4,%5,%6,%7}, {%8,%9}, {%0,%1,%2,%3};"
                 : "+f"(d[0]), "+f"(d[1]), "+f"(d[2]), "+f"(d[3])
                 : "r"(a[0]), "r"(a[1]), "r"(a[2]), "r"(a[3]),
                   "r"(b[0]), "r"(b[1]));
}
__device__ __forceinline__ uint32_t pack_bf16(float a, float b) {
    __nv_bfloat162 p = __floats2bfloat162_rn(a, b);
    return *(uint32_t*)&p;
}

// ---------------- LayerNorm: one block per token; emits bf16 ----------------
__global__ void __launch_bounds__(256) ln_kernel(const float* __restrict__ x,
                                                 const float* __restrict__ gamma,
                                                 const float* __restrict__ beta) {
    __shared__ float red[16];
    const int row = blockIdx.x;
    const int tid = threadIdx.x;
    const float4 v = ((const float4*)(x + (size_t)row * D_))[tid];
    float s  = v.x + v.y + v.z + v.w;
    float ss = v.x * v.x + v.y * v.y + v.z * v.z + v.w * v.w;
#pragma unroll
    for (int o = 16; o > 0; o >>= 1) {
        s  += __shfl_xor_sync(0xffffffffu, s, o);
        ss += __shfl_xor_sync(0xffffffffu, ss, o);
    }
    const int warp = tid >> 5, lane = tid & 31;
    if (lane == 0) { red[warp] = s; red[warp + 8] = ss; }
    __syncthreads();
    if (tid < 32) {
        float a = (tid < 8) ? red[tid] : 0.f;
        float b = (tid < 8) ? red[tid + 8] : 0.f;
#pragma unroll
        for (int o = 4; o > 0; o >>= 1) {
            a += __shfl_xor_sync(0xffffffffu, a, o);
            b += __shfl_xor_sync(0xffffffffu, b, o);
        }
        if (tid == 0) { red[0] = a; red[1] = b; }
    }
    __syncthreads();
    const float mu   = red[0] * (1.0f / D_);
    const float var  = red[1] * (1.0f / D_) - mu * mu;
    const float rstd = rsqrtf(var + 1e-5f);
    const float4 g  = ((const float4*)gamma)[tid];
    const float4 bb = ((const float4*)beta)[tid];
    const float o0 = (v.x - mu) * rstd * g.x + bb.x;
    const float o1 = (v.y - mu) * rstd * g.y + bb.y;
    const float o2 = (v.z - mu) * rstd * g.z + bb.z;
    const float o3 = (v.w - mu) * rstd * g.w + bb.w;
    const size_t off = (size_t)row * D_ + tid * 4;
    *(__nv_bfloat162*)(g_xnh + off)     = __floats2bfloat162_rn(o0, o1);
    *(__nv_bfloat162*)(g_xnh + off + 2) = __floats2bfloat162_rn(o2, o3);
}

// ---------------- W transpose to bf16: Wt[n][k] = W[k][n] --------------------
__global__ void __launch_bounds__(256) wsplit_kernel(const float* __restrict__ Wq,
                                                     const float* __restrict__ Wk,
                                                     const float* __restrict__ Wv) {
    __shared__ float t[32][33];
    const float* W = (blockIdx.z == 0) ? Wq : (blockIdx.z == 1) ? Wk : Wv;
    __nv_bfloat16* oh = g_wth + ((size_t)blockIdx.z << 20);
    const int tid = threadIdx.x;
    const int tx = tid & 31, ty = tid >> 5;
    const int bn = blockIdx.x * 32, bk = blockIdx.y * 32;
#pragma unroll
    for (int r = ty; r < 32; r += 8)
        t[r][tx] = W[(size_t)(bk + r) * 1024 + bn + tx];
    __syncthreads();
#pragma unroll
    for (int r = ty; r < 32; r += 8)
        oh[(size_t)(bn + r) * 1024 + bk + tx] = __float2bfloat16_rn(t[tx][r]);
}

// ---------------- QKV GEMM via mma.sync bf16 + fused epilogues ---------------
// Tile 128(M) x 128(N), BK=64, 3-stage cp.async, 256 threads, 2 CTAs/SM.
// 8 warps: warp (wm 0..1, wn 0..3) owns 64x32.
// mode = mode_base + blockIdx.z (0:q+softmax, 1:k, 2:v).
// Modes 1/2: fully-masked M-tiles skip the GEMM entirely (k=-1e6, v=0 fills
// are bit-identical downstream: exp underflows to 0; v*0 = 0).
#define OFF_A  0
#define OFF_B  16384
#define STG    32768
#define QK_SMEM (3 * STG + 1024)

__global__ void __launch_bounds__(256, 2)
qkv_mma(const float* __restrict__ bq, const float* __restrict__ bk_,
        const float* __restrict__ bv, const float* __restrict__ mask,
        int mode_base) {
    extern __shared__ char dsm[];
    const uint32_t base = (smem_u32(dsm) + 1023) & ~1023u;
    const int tid = threadIdx.x, lane = tid & 31, wid = tid >> 5;
    const int wm = wid & 1, wn = wid >> 1;
    const int mode = mode_base + blockIdx.z;
    const int n0 = blockIdx.x * 128;
    const size_t m0 = (size_t)blockIdx.y * 128;

    // ---- masked-tile fast path (k/v only): outputs of fully-masked rows are
    // never observed except through exact constants. Data-driven, any mask.
    if (mode != 0) {
        __shared__ int anyv;
        if (tid == 0) anyv = 0;
        __syncthreads();
        if (tid < 128 && mask[m0 + tid] != 0.f) anyv = 1;
        __syncthreads();
        if (!anyv) {
            __nv_bfloat16* __restrict__ C = (mode == 1) ? g_kb : g_vb;
            const uint32_t fl = (mode == 1) ? pack_bf16(NEGV, NEGV) : 0u;
            const uint4 f4 = make_uint4(fl, fl, fl, fl);
#pragma unroll
            for (int it = 0; it < 8; it++) {
                const int idx = it * 256 + tid;        // 0..2047
                const int r = idx >> 4, c = (idx & 15) * 8;
                *(uint4*)(C + (m0 + r) * 1024 + n0 + c) = f4;
            }
            return;
        }
    }

    const __nv_bfloat16* A = g_xnh;
    const __nv_bfloat16* Bw = g_wth + ((size_t)mode << 20);

    float acc[4][4][4];
#pragma unroll
    for (int i = 0; i < 4; i++)
#pragma unroll
        for (int j = 0; j < 4; j++)
#pragma unroll
            for (int q = 0; q < 4; q++) acc[i][j][q] = 0.f;

    auto issue = [&](int i) {
        const int k0 = i * 64;
        const uint32_t sb = base + (i % 3) * STG;
#pragma unroll
        for (int p = 0; p < 4; p++) {
            const int idx = p * 256 + tid;             // 0..1023
            const int r = idx >> 3, kc = idx & 7;
            const uint32_t sw = SW128(r * 128 + kc * 16);
            cp16(sb + OFF_A + sw, A + (m0 + r) * 1024 + k0 + kc * 8);
            cp16(sb + OFF_B + sw, Bw + (size_t)(n0 + r) * 1024 + k0 + kc * 8);
        }
        CP_COMMIT();
    };

    issue(0); issue(1);
    const int arow  = wm * 64 + (lane & 15);
    const int acolb = (lane >> 4) * 16;
    const int brow  = wn * 32 + (lane & 7) + ((lane & 16) ? 8 : 0);
    const int bcolb = (lane & 8) ? 16 : 0;

    for (int i = 0; i < 16; i++) {
        if (i + 2 < 16) CP_WAIT(1); else CP_WAIT(0);
        __syncthreads();               // stage (i-1) consumers drained
        if (i + 2 < 16) issue(i + 2);  // overwrites stage (i-1)%3: safe
        const uint32_t sb = base + (i % 3) * STG;

#pragma unroll
        for (int ks = 0; ks < 4; ks++) {
            const int kb = ks * 32;
            uint32_t ah[4][4];
#pragma unroll
            for (int mi = 0; mi < 4; mi++) {
                const uint32_t ao = SW128((arow + mi * 16) * 128 + kb + acolb);
                ldsm_x4(ah[mi], sb + OFF_A + ao);
            }
#pragma unroll
            for (int nb = 0; nb < 2; nb++) {
                const uint32_t bo = SW128((brow + nb * 16) * 128 + kb + bcolb);
                uint32_t bh[4];
                ldsm_x4(bh, sb + OFF_B + bo);
#pragma unroll
                for (int mi = 0; mi < 4; mi++)
#pragma unroll
                    for (int ns = 0; ns < 2; ns++)
                        mma16816(acc[mi][nb * 2 + ns], ah[mi], &bh[ns * 2]);
            }
        }
    }
    __syncthreads();                   // mainloop fully drained before reuse

    const int rl0 = wm * 64 + (lane >> 2);            // local row base
    const int cl0 = wn * 32 + (lane & 3) * 2;         // local col base

    if (mode == 0) {
        // ---- fused q softmax: tile = one head (128 cols) per CTA ----
        float* S = (float*)dsm;                        // 128 x 128 fp32 (64KB)
#pragma unroll
        for (int mi = 0; mi < 4; mi++) {
            const int r0 = rl0 + mi * 16;
#pragma unroll
            for (int ni = 0; ni < 4; ni++) {
                const int c = cl0 + ni * 8;
                *(float2*)&S[(r0)     * 128 + c] = make_float2(acc[mi][ni][0], acc[mi][ni][1]);
                *(float2*)&S[(r0 + 8) * 128 + c] = make_float2(acc[mi][ni][2], acc[mi][ni][3]);
            }
        }
        __syncthreads();
        const float4 bias4 = *(const float4*)(bq + n0 + lane * 4);
#pragma unroll
        for (int u = wid * 16; u < wid * 16 + 16; u++) {
            float4 v = *(const float4*)&S[u * 128 + lane * 4];
            v.x += bias4.x; v.y += bias4.y; v.z += bias4.z; v.w += bias4.w;
            float mx = fmaxf(fmaxf(v.x, v.y), fmaxf(v.z, v.w));
#pragma unroll
            for (int o = 16; o > 0; o >>= 1)
                mx = fmaxf(mx, __shfl_xor_sync(0xffffffffu, mx, o));
            v.x = __expf(v.x - mx); v.y = __expf(v.y - mx);
            v.z = __expf(v.z - mx); v.w = __expf(v.w - mx);
            float sm = v.x + v.y + v.z + v.w;
#pragma unroll
            for (int o = 16; o > 0; o >>= 1)
                sm += __shfl_xor_sync(0xffffffffu, sm, o);
            const float inv = 1.0f / sm;
            uint2 pk;
            pk.x = pack_bf16(v.x * inv, v.y * inv);
            pk.y = pack_bf16(v.z * inv, v.w * inv);
            *(uint2*)(g_qb + (m0 + u) * 1024 + n0 + lane * 4) = pk;
        }
    } else {
        const float* bias = (mode == 1) ? bk_ : bv;
        __nv_bfloat16* __restrict__ C = (mode == 1) ? g_kb : g_vb;
#pragma unroll
        for (int mi = 0; mi < 4; mi++) {
            const int r0 = (int)m0 + rl0 + mi * 16;
            const int r1 = r0 + 8;
            const float mk0 = mask[r0], mk1 = mask[r1];
            const float ma0 = (mode == 1) ? (1.0f - mk0) * NEGV : 0.f;
            const float ma1 = (mode == 1) ? (1.0f - mk1) * NEGV : 0.f;
            const float mm0 = (mode == 2) ? mk0 : 1.f;
            const float mm1 = (mode == 2) ? mk1 : 1.f;
#pragma unroll
            for (int ni = 0; ni < 4; ni++) {
                const int c = n0 + cl0 + ni * 8;
                const float b0 = bias[c], b1 = bias[c + 1];
                *(uint32_t*)(C + (size_t)r0 * 1024 + c) =
                    pack_bf16((acc[mi][ni][0] + b0 + ma0) * mm0,
                              (acc[mi][ni][1] + b1 + ma0) * mm0);
                *(uint32_t*)(C + (size_t)r1 * 1024 + c) =
                    pack_bf16((acc[mi][ni][2] + b0 + ma1) * mm1,
                              (acc[mi][ni][3] + b1 + ma1) * mm1);
            }
        }
    }
}

// ---------------- att partial via HMMA, double-buffered cp.async K+V --------
// Mask-gated tiles: fully-masked 32-t tiles skip loads AND compute.
#define NITER (T_ / NSPLIT / 32)       // 16
__global__ void __launch_bounds__(256) att_part_kernel(const float* __restrict__ mask) {
    __shared__ __align__(16) char Kb[2][32 * EP];
    __shared__ __align__(16) char Vb[2][32 * EP];
    __shared__ float Sred[8][128];
    __shared__ int valid[NITER];
    const int bh = blockIdx.x, sp = blockIdx.y;
    const int b = bh >> 3, h = bh & 7;
    const int tid = threadIdx.x, lane = tid & 31, wid = tid >> 5;
    const int wd = wid & 3, wl = wid >> 2;
    const int tstart = sp * (T_ / NSPLIT);

    // per-tile validity: thread tid covers t = tstart + 2*tid, +1
    if (tid < NITER) valid[tid] = 0;
    __syncthreads();
    {
        const int t = 2 * tid;
        if (mask[b * T_ + tstart + t] != 0.f || mask[b * T_ + tstart + t + 1] != 0.f)
            valid[t >> 5] = 1;         // benign race, all writers store 1
    }
    __syncthreads();

    float acc[2][8][4];
#pragma unroll
    for (int i = 0; i < 2; i++)
#pragma unroll
        for (int j = 0; j < 8; j++)
#pragma unroll
            for (int q = 0; q < 4; q++) acc[i][j][q] = 0.f;
    float ssum[4] = {0.f, 0.f, 0.f, 0.f};

    const uint32_t Kbase[2] = { smem_u32(Kb[0]), smem_u32(Kb[1]) };
    const uint32_t Vbase[2] = { smem_u32(Vb[0]), smem_u32(Vb[1]) };
    const size_t gbase = ((size_t)b * T_) * D_ + h * 128;
    const int dc = (tid & 31) * 4;

    auto issueKV = [&](int it, int buf) {
#pragma unroll
        for (int s = 0; s < 2; s++) {
            const int idx = s * 256 + tid;             // 0..511
            const int tr = idx >> 4, ch = idx & 15;
            const size_t go = gbase + (size_t)(tstart + it * 32 + tr) * D_ + ch * 8;
            cp16(Kbase[buf] + tr * EP + ch * 16, g_kb + go);
            cp16(Vbase[buf] + tr * EP + ch * 16, g_vb + go);
        }
        CP_COMMIT();
    };

    if (valid[0]) issueKV(0, 0);
    for (int i = 0; i < NITER; i++) {
        const int buf = i & 1;
        CP_WAIT(0);
        __syncthreads();               // data ready + prev iter fully done
        if (i + 1 < NITER && valid[i + 1]) issueKV(i + 1, (i + 1) & 1);
        if (!valid[i]) continue;

        // E = exp(k) in place, from SMEM; masked rows give exactly 0
#pragma unroll
        for (int s = 0; s < 4; s++) {
            const int tr = wid + s * 8;
            const uint32_t addr = tr * EP + dc * 2;
            const uint2 kp = *(const uint2*)(Kb[buf] + addr);
            const __nv_bfloat162 k01 = *(const __nv_bfloat162*)&kp.x;
            const __nv_bfloat162 k23 = *(const __nv_bfloat162*)&kp.y;
            const float e0 = __expf(__bfloat162float(k01.x));
            const float e1 = __expf(__bfloat162float(k01.y));
            const float e2 = __expf(__bfloat162float(k23.x));
            const float e3 = __expf(__bfloat162float(k23.y));
            ssum[0] += e0; ssum[1] += e1; ssum[2] += e2; ssum[3] += e3;
            uint2 pe;
            pe.x = pack_bf16(e0, e1);
            pe.y = pack_bf16(e2, e3);
            *(uint2*)(Kb[buf] + addr) = pe;
        }
        __syncthreads();
#pragma unroll
        for (int ks = 0; ks < 2; ks++) {
            uint32_t a[2][4], bf[4][4];
#pragma unroll
            for (int mi = 0; mi < 2; mi++) {
                const uint32_t ao = (uint32_t)((ks * 16 + ((lane & 16) ? 8 : 0)
                                   + (lane & 7)) * EP
                                   + (wd * 32 + mi * 16) * 2
                                   + ((lane & 8) ? 16 : 0));
                ldsm_x4t(a[mi], Kbase[buf] + ao);
            }
#pragma unroll
            for (int nb = 0; nb < 4; nb++) {
                const uint32_t bo = (uint32_t)((ks * 16 + ((lane & 8) ? 8 : 0)
                                   + (lane & 7)) * EP
                                   + (wl * 64 + nb * 16) * 2
                                   + ((lane & 16) ? 16 : 0));
                ldsm_x4t(bf[nb], Vbase[buf] + bo);
            }
#pragma unroll
            for (int mi = 0; mi < 2; mi++)
#pragma unroll
                for (int nb = 0; nb < 4; nb++)
#pragma unroll
                    for (int ns = 0; ns < 2; ns++)
                        mma16816(acc[mi][nb * 2 + ns], a[mi], &bf[nb][ns * 2]);
        }
    }

    const size_t obase = ((size_t)sp * 32 + bh) * 16384;
#pragma unroll
    for (int mi = 0; mi < 2; mi++) {
        const int d0 = wd * 32 + mi * 16 + (lane >> 2);
#pragma unroll
        for (int ni = 0; ni < 8; ni++) {
            const int l0 = wl * 64 + ni * 8 + (lane & 3) * 2;
            *(float2*)(g_attp + obase + (size_t)d0 * 128 + l0) =
                make_float2(acc[mi][ni][0], acc[mi][ni][1]);
            *(float2*)(g_attp + obase + (size_t)(d0 + 8) * 128 + l0) =
                make_float2(acc[mi][ni][2], acc[mi][ni][3]);
        }
    }
#pragma unroll
    for (int j = 0; j < 4; j++) Sred[wid][dc + j] = ssum[j];
    __syncthreads();
    if (tid < 128) {
        float s = 0.f;
#pragma unroll
        for (int r = 0; r < 8; r++) s += Sred[r][tid];
        g_Sp[(size_t)sp * 4096 + bh * 128 + tid] = s;
    }
}

// ---------------- att reduce: sum partials, normalize, emit bf16 -------------
__global__ void __launch_bounds__(256) att_reduce_kernel() {
    __shared__ float Ss[16];
    const int bh = blockIdx.x, ch = blockIdx.y;
    const int tid = threadIdx.x;
    if (tid < 16) {
        const int d = ch * 16 + tid;
        float s = 0.f;
#pragma unroll
        for (int p = 0; p < NSPLIT; p++) s += g_Sp[(size_t)p * 4096 + bh * 128 + d];
        Ss[tid] = 1.0f / s;
    }
    __syncthreads();
    const int e0 = ch * 2048;
#pragma unroll
    for (int q = 0; q < 8; q++) {
        const int e = e0 + q * 256 + tid;
        float s = 0.f;
#pragma unroll
        for (int p = 0; p < NSPLIT; p++) s += g_attp[((size_t)p * 32 + bh) * 16384 + e];
        g_attb[(size_t)bh * 16384 + e] =
            __float2bfloat16_rn(s * Ss[(e >> 7) - ch * 16]);
    }
}

// ---------------- y = q_sm @ att via HMMA, out = x + y -----------------------
#define YG_SMEM (2 * 128 * EP + 256)
__global__ void __launch_bounds__(256) ygemm_kernel(const float* __restrict__ x,
                                                    float* __restrict__ out) {
    extern __shared__ char ydsm[];
    const uint32_t qs = (smem_u32(ydsm) + 15) & ~15u;
    const uint32_t as = qs + 128 * EP;
    const int bh = blockIdx.y, mt = blockIdx.x;
    const int b = bh >> 3, h = bh & 7;
    const int tid = threadIdx.x, lane = tid & 31, wid = tid >> 5;
    const int wm = wid & 3, wl = wid >> 2;

    const size_t qgbase = ((size_t)b * T_ + mt * 128) * D_ + h * 128;
    const size_t agbase = (size_t)bh * 16384;
#pragma unroll
    for (int p = 0; p < 8; p++) {
        const int idx = p * 256 + tid;
        const int r = idx >> 4, c8 = idx & 15;
        cp16(qs + r * EP + c8 * 16, g_qb + qgbase + (size_t)r * 1024 + c8 * 8);
        cp16(as + r * EP + c8 * 16, g_attb + agbase + (size_t)r * 128 + c8 * 8);
    }
    CP_COMMIT();
    CP_WAIT(0);
    __syncthreads();

    float acc[2][8][4];
#pragma unroll
    for (int i = 0; i < 2; i++)
#pragma unroll
        for (int j = 0; j < 8; j++)
#pragma unroll
            for (int q = 0; q < 4; q++) acc[i][j][q] = 0.f;

#pragma unroll
    for (int ks = 0; ks < 8; ks++) {
        uint32_t a[2][4], bf[4][4];
#pragma unroll
        for (int mi = 0; mi < 2; mi++) {
            const uint32_t ao = (uint32_t)((wm * 32 + mi * 16 + (lane & 15)) * EP
                               + ks * 32 + ((lane & 16) ? 16 : 0));
            ldsm_x4(a[mi], qs + ao);
        }
#pragma unroll
        for (int nb = 0; nb < 4; nb++) {
            const uint32_t bo = (uint32_t)((ks * 16 + ((lane & 8) ? 8 : 0)
                               + (lane & 7)) * EP
                               + (wl * 64 + nb * 16) * 2
                               + ((lane & 16) ? 16 : 0));
            ldsm_x4t(bf[nb], as + bo);
        }
#pragma unroll
        for (int mi = 0; mi < 2; mi++)
#pragma unroll
            for (int nb = 0; nb < 4; nb++)
#pragma unroll
                for (int ns = 0; ns < 2; ns++)
                    mma16816(acc[mi][nb * 2 + ns], a[mi], &bf[nb][ns * 2]);
    }

#pragma unroll
    for (int mi = 0; mi < 2; mi++) {
        const size_t row0 = (size_t)b * T_ + mt * 128 + wm * 32 + mi * 16 + (lane >> 2);
        const size_t row1 = row0 + 8;
#pragma unroll
        for (int ni = 0; ni < 8; ni++) {
            const int c = h * 128 + wl * 64 + ni * 8 + (lane & 3) * 2;
            const float2 x0 = *(const float2*)(x + row0 * 1024 + c);
            const float2 x1 = *(const float2*)(x + row1 * 1024 + c);
            float2 o0, o1;
            o0.x = acc[mi][ni][0] + x0.x; o0.y = acc[mi][ni][1] + x0.y;
            o1.x = acc[mi][ni][2] + x1.x; o1.y = acc[mi][ni][3] + x1.y;
            *(float2*)(out + row0 * 1024 + c) = o0;
            *(float2*)(out + row1 * 1024 + c) = o1;
        }
    }
}

// ---------------- launcher: q owns machine post-kv; att fills its slack ------
extern "C" void kernel_launch(void* const* d_in, const int* in_sizes, int n_in,
                              void* d_out, int out_size) {
    const float* x     = (const float*)d_in[0];
    const float* mask  = (const float*)d_in[1];
    const float* Wq    = (const float*)d_in[2];
    const float* bq    = (const float*)d_in[3];
    const float* Wk    = (const float*)d_in[4];
    const float* bk    = (const float*)d_in[5];
    const float* Wv    = (const float*)d_in[6];
    const float* bv    = (const float*)d_in[7];
    const float* gamma = (const float*)d_in[8];
    const float* beta  = (const float*)d_in[9];
    float* out = (float*)d_out;

    static cudaStream_t s1;
    static cudaEvent_t evStart, evW, evKV, evATT;
    static int init_done = 0;
    if (!init_done) {
        cudaFuncSetAttribute(qkv_mma, cudaFuncAttributeMaxDynamicSharedMemorySize,
                             QK_SMEM);
        cudaFuncSetAttribute(ygemm_kernel,
                             cudaFuncAttributeMaxDynamicSharedMemorySize, YG_SMEM);
        int prLow, prHigh;
        cudaDeviceGetStreamPriorityRange(&prLow, &prHigh);
        cudaStreamCreateWithPriority(&s1, cudaStreamNonBlocking, prLow);
        cudaEventCreateWithFlags(&evStart, cudaEventDisableTiming);
        cudaEventCreateWithFlags(&evW, cudaEventDisableTiming);
        cudaEventCreateWithFlags(&evKV, cudaEventDisableTiming);
        cudaEventCreateWithFlags(&evATT, cudaEventDisableTiming);
        init_done = 1;
    }

    // Capture-legal fork: s1 begins by waiting on an event from stream 0.
    cudaEventRecord(evStart, 0);
    cudaStreamWaitEvent(s1, evStart, 0);

    // s1 (low prio): wsplit (needs only W)
    wsplit_kernel<<<dim3(32, 32, 3), 256, 0, s1>>>(Wq, Wk, Wv);
    cudaEventRecord(evW, s1);

    // stream 0: ln (needs only x)
    ln_kernel<<<NTOK, 256>>>(x, gamma, beta);
    cudaStreamWaitEvent(0, evW, 0);

    // stream 0: kv GEMM (modes 1,2), then q GEMM immediately (owns machine)
    qkv_mma<<<dim3(8, 128, 2), 256, QK_SMEM>>>(bq, bk, bv, mask, 1);
    cudaEventRecord(evKV, 0);
    qkv_mma<<<dim3(8, 128, 1), 256, QK_SMEM>>>(bq, bk, bv, mask, 0);

    // s1 (low prio): att chain fills q's idle issue slots
    cudaStreamWaitEvent(s1, evKV, 0);
    att_part_kernel<<<dim3(32, NSPLIT), 256, 0, s1>>>(mask);
    att_reduce_kernel<<<dim3(32, 8), 256, 0, s1>>>();
    cudaEventRecord(evATT, s1);

    // join: ygemm needs q (stream 0 order) and attb (s1)
    cudaStreamWaitEvent(0, evATT, 0);
    ygemm_kernel<<<dim3(32, 32), 256, YG_SMEM>>>(x, out);
}